// round 12
// baseline (speedup 1.0000x reference)
#include <cuda_runtime.h>
#include <cuda_fp16.h>
#include <math.h>
#include <stdint.h>

#define BB 4
#define LQ 2048
#define LK 2048
#define DM 1024
#define NH 16
#define DK 64
#define NEGV -1000000000.0f

// Pre-split fp16 hi/lo projected tensors (outputs of proj): [B*LEN, NH*DK]
__device__ __half g_qh[BB * LQ * NH * DK];
__device__ __half g_ql[BB * LQ * NH * DK];
__device__ __half g_kh[BB * LK * NH * DK];
__device__ __half g_kl[BB * LK * NH * DK];
__device__ __half g_vh[BB * LK * NH * DK];
__device__ __half g_vl[BB * LK * NH * DK];

// Pre-split inputs and weights for the projection GEMMs.
__device__ __half i_qh[BB * LQ * DM], i_ql[BB * LQ * DM];
__device__ __half i_kh[BB * LK * DM], i_kl[BB * LK * DM];
__device__ __half i_vh[BB * LK * DM], i_vl[BB * LK * DM];
__device__ __half w_qh[NH * DK * DM], w_ql[NH * DK * DM];
__device__ __half w_kh[NH * DK * DM], w_kl[NH * DK * DM];
__device__ __half w_vh[NH * DK * DM], w_vl[NH * DK * DM];

__device__ __forceinline__ uint32_t smem_u32(const void* p) {
    uint32_t a;
    asm("{ .reg .u64 t; cvta.to.shared.u64 t, %1; cvt.u32.u64 %0, t; }"
        : "=r"(a) : "l"(p));
    return a;
}
__device__ __forceinline__ void ldm4(unsigned r[4], uint32_t a) {
    asm volatile("ldmatrix.sync.aligned.m8n8.x4.shared.b16 {%0,%1,%2,%3}, [%4];"
        : "=r"(r[0]), "=r"(r[1]), "=r"(r[2]), "=r"(r[3]) : "r"(a));
}
__device__ __forceinline__ void ldm4t(unsigned r[4], uint32_t a) {
    asm volatile("ldmatrix.sync.aligned.m8n8.x4.trans.shared.b16 {%0,%1,%2,%3}, [%4];"
        : "=r"(r[0]), "=r"(r[1]), "=r"(r[2]), "=r"(r[3]) : "r"(a));
}
__device__ __forceinline__ void mma16(float c[4], const unsigned a[4],
                                      unsigned b0, unsigned b1) {
    asm volatile(
        "mma.sync.aligned.m16n8k16.row.col.f32.f16.f16.f32 "
        "{%0,%1,%2,%3},{%4,%5,%6,%7},{%8,%9},{%0,%1,%2,%3};"
        : "+f"(c[0]), "+f"(c[1]), "+f"(c[2]), "+f"(c[3])
        : "r"(a[0]), "r"(a[1]), "r"(a[2]), "r"(a[3]), "r"(b0), "r"(b1));
}
__device__ __forceinline__ void split2x(float a, float b, uint32_t& hi, uint32_t& lo) {
    __half2 h = __floats2half2_rn(a, b);
    float2 hf = __half22float2(h);
    __half2 l = __floats2half2_rn(a - hf.x, b - hf.y);
    hi = *(uint32_t*)&h;
    lo = *(uint32_t*)&l;
}
__device__ __forceinline__ uint32_t pack_h2(float a, float b) {
    __half2 h = __floats2half2_rn(a, b);
    return *(uint32_t*)&h;
}
#define CP16(dst, src) \
    asm volatile("cp.async.cg.shared.global [%0], [%1], 16;" \
                 :: "r"(dst), "l"(src) : "memory")
#define CPCOMMIT() asm volatile("cp.async.commit_group;" ::: "memory")
#define CPWAIT0()  asm volatile("cp.async.wait_group 0;" ::: "memory")
#define CPWAIT1()  asm volatile("cp.async.wait_group 1;" ::: "memory")

// ---------------------------------------------------------------------------
// Pre-split: fp32 inputs + weights -> fp16 hi/lo pairs (R10-proven, ~35us).
// ---------------------------------------------------------------------------
__global__ __launch_bounds__(256) void presplit(
    const float* __restrict__ Qin, const float* __restrict__ Kin,
    const float* __restrict__ Vin,
    const float* __restrict__ Wq, const float* __restrict__ Wk,
    const float* __restrict__ Wv)
{
    const float *A, *W;
    __half *ah, *al, *wh, *wl;
    if (blockIdx.z == 0)      { A = Qin; W = Wq; ah = i_qh; al = i_ql; wh = w_qh; wl = w_ql; }
    else if (blockIdx.z == 1) { A = Kin; W = Wk; ah = i_kh; al = i_kl; wh = w_kh; wl = w_kl; }
    else                      { A = Vin; W = Wv; ah = i_vh; al = i_vl; wh = w_vh; wl = w_vl; }

    const int stride = gridDim.x * blockDim.x;
    const int t0 = blockIdx.x * blockDim.x + threadIdx.x;

    const int NA = BB * LQ * DM / 4;
    for (int idx = t0; idx < NA; idx += stride) {
        float4 v = ((const float4*)A)[idx];
        uint32_t h0, l0, h1, l1;
        split2x(v.x, v.y, h0, l0);
        split2x(v.z, v.w, h1, l1);
        ((uint2*)ah)[idx] = make_uint2(h0, h1);
        ((uint2*)al)[idx] = make_uint2(l0, l1);
    }
    const int NW = NH * DK * DM / 4;
    for (int idx = t0; idx < NW; idx += stride) {
        float4 v = ((const float4*)W)[idx];
        uint32_t h0, l0, h1, l1;
        split2x(v.x, v.y, h0, l0);
        split2x(v.z, v.w, h1, l1);
        ((uint2*)wh)[idx] = make_uint2(h0, h1);
        ((uint2*)wl)[idx] = make_uint2(l0, l1);
    }
}

// ---------------------------------------------------------------------------
// Projection GEMM, 3-stage cp.async pipeline from pre-split halves.
// z = 0:Q (scale log2(e)/8), 1:K, 2:V. BM=128 BN=64 BK=32, 3-term HMMA.
// smem/stage: Ah/Al 128x40 + Wh/Wl 64x40 halves = 30720 B; 3 stages = 92160 B.
// ---------------------------------------------------------------------------
#define PAH_OFF 0        // halves
#define PAL_OFF 5120
#define PWH_OFF 10240
#define PWL_OFF 12800
#define PSTAGE  15360    // halves per stage
#define PROJ_SMEM (3 * PSTAGE * 2)

__global__ __launch_bounds__(256, 2) void proj_pipe(
    const float* __restrict__ bq, const float* __restrict__ bv)
{
    const __half *Agh, *Agl, *Wgh, *Wgl;
    const float* bias;
    __half *Ch, *Cl;
    float scale;
    if (blockIdx.z == 0)      { Agh = i_qh; Agl = i_ql; Wgh = w_qh; Wgl = w_ql;
                                bias = bq;      Ch = g_qh; Cl = g_ql;
                                scale = 0.18033688f; }   // (1/8)*log2(e)
    else if (blockIdx.z == 1) { Agh = i_kh; Agl = i_kl; Wgh = w_kh; Wgl = w_kl;
                                bias = nullptr; Ch = g_kh; Cl = g_kl; scale = 1.f; }
    else                      { Agh = i_vh; Agl = i_vl; Wgh = w_vh; Wgl = w_vl;
                                bias = bv;      Ch = g_vh; Cl = g_vl; scale = 1.f; }

    extern __shared__ __half psm[];
    const uint32_t smb = smem_u32(psm);

    const int tid = threadIdx.x, warp = tid >> 5, lane = tid & 31;
    const int g = lane >> 2, tg = lane & 3;
    const int wm = warp & 3, wn = warp >> 2;
    const int bm = blockIdx.y * 128, bn = blockIdx.x * 64;
    const int lrow = lane & 15, lcol8 = (lane >> 4) << 3;

    // copy geometry: A thread -> (row tid>>1, 16-half span at (tid&1)*16)
    //                W thread -> (row tid>>2, 8-half span at (tid&3)*8)
    const int arow = tid >> 1, acol = (tid & 1) * 16;
    const int wrow = tid >> 2, wcol = (tid & 3) * 8;

    float acc[2][4][4];
#pragma unroll
    for (int i = 0; i < 2; ++i)
#pragma unroll
        for (int j = 0; j < 4; ++j)
#pragma unroll
            for (int t = 0; t < 4; ++t) acc[i][j][t] = 0.f;

#define PCOPY(ST, K0) do {                                                    \
    uint32_t sbase = smb + (uint32_t)(ST) * (PSTAGE * 2);                     \
    uint32_t da = sbase + PAH_OFF * 2 + (uint32_t)(arow * 40 + acol) * 2;     \
    const __half* sah = Agh + (size_t)(bm + arow) * DM + (K0) + acol;         \
    CP16(da, sah); CP16(da + 16, sah + 8);                                    \
    uint32_t dal = sbase + PAL_OFF * 2 + (uint32_t)(arow * 40 + acol) * 2;    \
    const __half* sal = Agl + (size_t)(bm + arow) * DM + (K0) + acol;         \
    CP16(dal, sal); CP16(dal + 16, sal + 8);                                  \
    uint32_t dwh = sbase + PWH_OFF * 2 + (uint32_t)(wrow * 40 + wcol) * 2;    \
    CP16(dwh, Wgh + (size_t)(bn + wrow) * DM + (K0) + wcol);                  \
    uint32_t dwl = sbase + PWL_OFF * 2 + (uint32_t)(wrow * 40 + wcol) * 2;    \
    CP16(dwl, Wgl + (size_t)(bn + wrow) * DM + (K0) + wcol);                  \
    CPCOMMIT();                                                               \
} while (0)

#define PITER(ST, K0) do {                                                    \
    __syncthreads();  /* buffer (ST+2)%3 fully consumed (computed last iter) */ \
    if ((K0) + 64 < DM) PCOPY(((ST) + 2) % 3, (K0) + 64);                     \
    else CPCOMMIT();                                                          \
    CPWAIT1();        /* stage ST (and ST+1) copies complete */               \
    __syncthreads();                                                          \
    uint32_t sbase = smb + (uint32_t)(ST) * (PSTAGE * 2);                     \
    const uint32_t ahb = sbase + PAH_OFF * 2;                                 \
    const uint32_t alb = sbase + PAL_OFF * 2;                                 \
    const uint32_t whb = sbase + PWH_OFF * 2;                                 \
    const uint32_t wlb = sbase + PWL_OFF * 2;                                 \
    _Pragma("unroll")                                                         \
    for (int kk = 0; kk < 32; kk += 16) {                                     \
        unsigned a_h[2][4], a_l[2][4], b_h[2][4], b_l[2][4];                  \
        _Pragma("unroll")                                                     \
        for (int mf = 0; mf < 2; ++mf) {                                      \
            uint32_t off = (uint32_t)((wm * 32 + mf * 16 + lrow) * 40 + kk + lcol8) * 2; \
            ldm4(a_h[mf], ahb + off);                                         \
            ldm4(a_l[mf], alb + off);                                         \
        }                                                                     \
        _Pragma("unroll")                                                     \
        for (int nh = 0; nh < 2; ++nh) {                                      \
            uint32_t off = (uint32_t)((wn * 32 + nh * 16 + lrow) * 40 + kk + lcol8) * 2; \
            ldm4(b_h[nh], whb + off);                                         \
            ldm4(b_l[nh], wlb + off);                                         \
        }                                                                     \
        _Pragma("unroll")                                                     \
        for (int mf = 0; mf < 2; ++mf)                                        \
            _Pragma("unroll")                                                 \
            for (int nh = 0; nh < 2; ++nh)                                    \
                _Pragma("unroll")                                             \
                for (int j = 0; j < 2; ++j) {                                 \
                    int nf = nh * 2 + j;                                      \
                    mma16(acc[mf][nf], a_h[mf], b_h[nh][j], b_h[nh][2 + j]);  \
                    mma16(acc[mf][nf], a_l[mf], b_h[nh][j], b_h[nh][2 + j]);  \
                    mma16(acc[mf][nf], a_h[mf], b_l[nh][j], b_l[nh][2 + j]);  \
                }                                                             \
    }                                                                         \
} while (0)

    // prologue: stage 0 <- k0=0, stage 1 <- k0=32
    PCOPY(0, 0);
    PCOPY(1, 32);

    // 32 K-iters: 10 full triples + 2 tail iters
    int k0 = 0;
#pragma unroll 1
    for (int i = 0; i < 10; ++i) {
        PITER(0, k0); k0 += 32;
        PITER(1, k0); k0 += 32;
        PITER(2, k0); k0 += 32;
    }
    PITER(0, 960);
    PITER(1, 992);

#undef PITER
#undef PCOPY

    // Epilogue: bias + scale, store pre-split hi/lo.
#pragma unroll
    for (int mf = 0; mf < 2; ++mf)
#pragma unroll
        for (int nf = 0; nf < 4; ++nf) {
            int r = bm + wm * 32 + mf * 16 + g;
            int c = bn + wn * 32 + (nf >> 1) * 16 + (nf & 1) * 8 + 2 * tg;
            float b0 = 0.f, b1 = 0.f;
            if (bias) { float2 bb = *(const float2*)(bias + c); b0 = bb.x; b1 = bb.y; }
            uint32_t hi, lo;
            split2x((acc[mf][nf][0] + b0) * scale, (acc[mf][nf][1] + b1) * scale, hi, lo);
            *(uint32_t*)(Ch + (size_t)r * (NH * DK) + c) = hi;
            *(uint32_t*)(Cl + (size_t)r * (NH * DK) + c) = lo;
            split2x((acc[mf][nf][2] + b0) * scale, (acc[mf][nf][3] + b1) * scale, hi, lo);
            *(uint32_t*)(Ch + (size_t)(r + 8) * (NH * DK) + c) = hi;
            *(uint32_t*)(Cl + (size_t)(r + 8) * (NH * DK) + c) = lo;
        }
}

// ---------------------------------------------------------------------------
// Flash attention (R11 version, unchanged — proven 535us).
// ---------------------------------------------------------------------------
#define ATTN_SMEM 92192
#define BUFB 4608   // bytes per KV buffer step (2304 halves)

__global__ __launch_bounds__(256, 2) void attn_pipe(
    const int* __restrict__ mask, float* __restrict__ out)
{
    extern __shared__ __half sm[];
    const uint32_t smb = smem_u32(sm);
    const uint32_t qh_base = smb;
    const uint32_t ql_base = smb + 9216 * 2;
    const uint32_t kh0 = smb + 18432 * 2;
    const uint32_t kl0 = smb + 25344 * 2;
    const uint32_t vh0 = smb + 32256 * 2;
    const uint32_t vl0 = smb + 39168 * 2;
    uint32_t* MBW = (uint32_t*)((char*)sm + 92160);

    const int tid = threadIdx.x, warp = tid >> 5, lane = tid & 31;
    const int g = lane >> 2, tg = lane & 3;
    const int b = blockIdx.z, h = blockIdx.y;
    const int q0 = blockIdx.x * 128;

    const int lrow = lane & 15, lcol8 = (lane >> 4) << 3;
    const int kvr  = (lane & 7) + ((lane >> 4) << 3);
    const int dcol = ((lane >> 3) & 1) * 8;
    const int cr = tid >> 3, cc = (tid & 7) * 8;
    const uint32_t cpo = (uint32_t)(cr * 72 + cc) * 2;

    float o[8][4];
#pragma unroll
    for (int i = 0; i < 8; ++i)
#pragma unroll
        for (int j = 0; j < 4; ++j) o[i][j] = 0.f;
    float mrA = -INFINITY, mrB = -INFINITY, lrA = 0.f, lrB = 0.f;
    float sa[4][4], sa_n[4][4];

    {
        int qrow = tid >> 1, qcb = (tid & 1) * 32;
        size_t qg = (size_t)(b * LQ + q0 + qrow) * (NH * DK) + h * DK + qcb;
        uint32_t qdh = qh_base + (uint32_t)(qrow * 72 + qcb) * 2;
        uint32_t qdl = ql_base + (uint32_t)(qrow * 72 + qcb) * 2;
#pragma unroll
        for (int j = 0; j < 4; ++j) {
            CP16(qdh + j * 16, g_qh + qg + j * 8);
            CP16(qdl + j * 16, g_ql + qg + j * 8);
        }
        size_t g0 = (size_t)(b * LK + cr) * (NH * DK) + h * DK + cc;
        CP16(kh0 + cpo, g_kh + g0); CP16(kl0 + cpo, g_kl + g0);
        CP16(vh0 + cpo, g_vh + g0); CP16(vl0 + cpo, g_vl + g0);
        size_t g1 = (size_t)(b * LK + 32 + cr) * (NH * DK) + h * DK + cc;
        CP16(kh0 + BUFB + cpo, g_kh + g1); CP16(kl0 + BUFB + cpo, g_kl + g1);
        CP16(vh0 + BUFB + cpo, g_vh + g1); CP16(vl0 + BUFB + cpo, g_vl + g1);
        CPCOMMIT();
        if (warp == 0) {
            uint32_t b0 = __ballot_sync(0xffffffffu, mask[b * LK + lane] != 0);
            uint32_t b1 = __ballot_sync(0xffffffffu, mask[b * LK + 32 + lane] != 0);
            if (lane == 0) { MBW[0] = b0; MBW[1] = b1; }
        }
        CPWAIT0();
        __syncthreads();
    }

#define S_MMA(DST, BIDX) do {                                                 \
    _Pragma("unroll")                                                         \
    for (int nf = 0; nf < 4; ++nf)                                            \
        { DST[nf][0]=0.f; DST[nf][1]=0.f; DST[nf][2]=0.f; DST[nf][3]=0.f; }   \
    _Pragma("unroll")                                                         \
    for (int kk = 0; kk < 4; ++kk) {                                          \
        unsigned qa_h[4], qa_l[4];                                            \
        uint32_t qoff = (uint32_t)((warp * 16 + lrow) * 72 + kk * 16 + lcol8) * 2; \
        ldm4(qa_h, qh_base + qoff);                                           \
        ldm4(qa_l, ql_base + qoff);                                           \
        _Pragma("unroll")                                                     \
        for (int nh = 0; nh < 2; ++nh) {                                      \
            unsigned kbh[4], kbl[4];                                          \
            uint32_t koff = (uint32_t)((nh * 16 + lrow) * 72 + kk * 16 + lcol8) * 2; \
            ldm4(kbh, kh0 + (BIDX) * BUFB + koff);                            \
            ldm4(kbl, kl0 + (BIDX) * BUFB + koff);                            \
            _Pragma("unroll")                                                 \
            for (int j = 0; j < 2; ++j) {                                     \
                int nf = nh * 2 + j;                                          \
                mma16(DST[nf], qa_h, kbh[j], kbh[2 + j]);                     \
                mma16(DST[nf], qa_l, kbh[j], kbh[2 + j]);                     \
                mma16(DST[nf], qa_h, kbl[j], kbl[2 + j]);                     \
            }                                                                 \
        }                                                                     \
    }                                                                         \
} while (0)

#define SOFTMAX_PV(BIDX) do {                                                 \
    const uint32_t mb = MBW[BIDX];                                            \
    float mA = NEGV, mBv = NEGV;                                              \
    _Pragma("unroll")                                                         \
    for (int nf = 0; nf < 4; ++nf) {                                          \
        int c0 = nf * 8 + 2 * tg;                                             \
        bool k0 = (mb >> c0) & 1u;                                            \
        bool k1 = (mb >> (c0 + 1)) & 1u;                                      \
        sa[nf][0] = k0 ? sa[nf][0] : NEGV;                                    \
        sa[nf][1] = k1 ? sa[nf][1] : NEGV;                                    \
        sa[nf][2] = k0 ? sa[nf][2] : NEGV;                                    \
        sa[nf][3] = k1 ? sa[nf][3] : NEGV;                                    \
        mA = fmaxf(mA, fmaxf(sa[nf][0], sa[nf][1]));                          \
        mBv = fmaxf(mBv, fmaxf(sa[nf][2], sa[nf][3]));                        \
    }                                                                         \
    mA = fmaxf(mA, __shfl_xor_sync(0xffffffffu, mA, 1));                      \
    mA = fmaxf(mA, __shfl_xor_sync(0xffffffffu, mA, 2));                      \
    mBv = fmaxf(mBv, __shfl_xor_sync(0xffffffffu, mBv, 1));                   \
    mBv = fmaxf(mBv, __shfl_xor_sync(0xffffffffu, mBv, 2));                   \
    float mnA = fmaxf(mrA, mA), mnB = fmaxf(mrB, mBv);                        \
    float alA = exp2f(mrA - mnA), alB = exp2f(mrB - mnB);                     \
    mrA = mnA; mrB = mnB;                                                     \
    unsigned pah[2][4];                                                       \
    float lsA = 0.f, lsB = 0.f;                                               \
    _Pragma("unroll")                                                         \
    for (int jk = 0; jk < 2; ++jk) {                                          \
        _Pragma("unroll")                                                     \
        for (int t2 = 0; t2 < 2; ++t2) {                                      \
            int nf = jk * 2 + t2;                                             \
            float p0 = exp2f(sa[nf][0] - mnA);                                \
            float p1 = exp2f(sa[nf][1] - mnA);                                \
            float p2 = exp2f(sa[nf][2] - mnB);                                \
            float p3 = exp2f(sa[nf][3] - mnB);                                \
            lsA += p0 + p1; lsB += p2 + p3;                                   \
            pah[jk][2 * t2]     = pack_h2(p0, p1);                            \
            pah[jk][2 * t2 + 1] = pack_h2(p2, p3);                            \
        }                                                                     \
    }                                                                         \
    lsA += __shfl_xor_sync(0xffffffffu, lsA, 1);                              \
    lsA += __shfl_xor_sync(0xffffffffu, lsA, 2);                              \
    lsB += __shfl_xor_sync(0xffffffffu, lsB, 1);                              \
    lsB += __shfl_xor_sync(0xffffffffu, lsB, 2);                              \
    lrA = lrA * alA + lsA;                                                    \
    lrB = lrB * alB + lsB;                                                    \
    _Pragma("unroll")                                                         \
    for (int nf = 0; nf < 8; ++nf) {                                          \
        o[nf][0] *= alA; o[nf][1] *= alA;                                     \
        o[nf][2] *= alB; o[nf][3] *= alB;                                     \
    }                                                                         \
    _Pragma("unroll")                                                         \
    for (int jk = 0; jk < 2; ++jk) {                                          \
        _Pragma("unroll")                                                     \
        for (int dh = 0; dh < 4; ++dh) {                                      \
            unsigned vbh[4], vbl[4];                                          \
            uint32_t voff = (uint32_t)((jk * 16 + kvr) * 72 + dh * 16 + dcol) * 2; \
            ldm4t(vbh, vh0 + (BIDX) * BUFB + voff);                           \
            ldm4t(vbl, vl0 + (BIDX) * BUFB + voff);                           \
            _Pragma("unroll")                                                 \
            for (int j = 0; j < 2; ++j) {                                     \
                int nf = dh * 2 + j;                                          \
                mma16(o[nf], pah[jk], vbh[j], vbh[2 + j]);                    \
                mma16(o[nf], pah[jk], vbl[j], vbl[2 + j]);                    \
            }                                                                 \
        }                                                                     \
    }                                                                         \
} while (0)

#define ITER(T, B, B1, B2) do {                                               \
    __syncthreads();                                                          \
    if ((T) + 2 < 64) {                                                       \
        int ktt = ((T) + 2) * 32;                                             \
        size_t goff = (size_t)(b * LK + ktt + cr) * (NH * DK) + h * DK + cc;  \
        CP16(kh0 + (B2) * BUFB + cpo, g_kh + goff);                           \
        CP16(kl0 + (B2) * BUFB + cpo, g_kl + goff);                           \
        CP16(vh0 + (B2) * BUFB + cpo, g_vh + goff);                           \
        CP16(vl0 + (B2) * BUFB + cpo, g_vl + goff);                           \
        if (warp == 0) {                                                      \
            uint32_t bal = __ballot_sync(0xffffffffu,                         \
                                mask[b * LK + ktt + lane] != 0);              \
            if (lane == 0) MBW[B2] = bal;                                     \
        }                                                                     \
    }                                                                         \
    CPCOMMIT();                                                               \
    CPWAIT1();                                                                \
    __syncthreads();                                                          \
    S_MMA(sa_n, B1);                                                          \
    SOFTMAX_PV(B);                                                            \
    _Pragma("unroll")                                                         \
    for (int nf = 0; nf < 4; ++nf) {                                          \
        sa[nf][0] = sa_n[nf][0]; sa[nf][1] = sa_n[nf][1];                     \
        sa[nf][2] = sa_n[nf][2]; sa[nf][3] = sa_n[nf][3];                     \
    }                                                                         \
} while (0)

    S_MMA(sa, 0);

    int t = 0;
#pragma unroll 1
    for (int i = 0; i < 21; ++i) {
        ITER(t, 0, 1, 2); ++t;
        ITER(t, 1, 2, 0); ++t;
        ITER(t, 2, 0, 1); ++t;
    }
    SOFTMAX_PV(0);

#undef ITER
#undef SOFTMAX_PV
#undef S_MMA

    {
        float iA = 1.f / lrA, iB = 1.f / lrB;
        float* o0 = out + (size_t)(b * LQ + q0 + warp * 16 + g) * (NH * DK) + h * DK;
        float* o1 = o0 + (size_t)8 * (NH * DK);
#pragma unroll
        for (int nf = 0; nf < 8; ++nf) {
            int c = (nf >> 1) * 16 + (nf & 1) * 8 + 2 * tg;
            *(float2*)(o0 + c) = make_float2(o[nf][0] * iA, o[nf][1] * iA);
            *(float2*)(o1 + c) = make_float2(o[nf][2] * iB, o[nf][3] * iB);
        }
    }
}

// ---------------------------------------------------------------------------
extern "C" void kernel_launch(void* const* d_in, const int* in_sizes, int n_in,
                              void* d_out, int out_size)
{
    const float* Q    = (const float*)d_in[0];
    const float* K    = (const float*)d_in[1];
    const float* V    = (const float*)d_in[2];
    const int*   mask = (const int*)d_in[3];
    const float* Wq   = (const float*)d_in[4];
    const float* bq   = (const float*)d_in[5];
    const float* Wk   = (const float*)d_in[6];
    const float* Wv   = (const float*)d_in[7];
    const float* bv   = (const float*)d_in[8];
    float* out = (float*)d_out;

    cudaFuncSetAttribute(proj_pipe, cudaFuncAttributeMaxDynamicSharedMemorySize,
                         PROJ_SMEM);
    cudaFuncSetAttribute(attn_pipe, cudaFuncAttributeMaxDynamicSharedMemorySize,
                         ATTN_SMEM);

    presplit<<<dim3(512, 1, 3), 256>>>(Q, K, V, Wq, Wk, Wv);

    dim3 gproj((NH * DK) / 64, (BB * LQ) / 128, 3);  // (16, 64, 3)
    proj_pipe<<<gproj, 256, PROJ_SMEM>>>(bq, bv);

    dim3 gattn(LQ / 128, NH, BB);  // (16, 16, 4)
    attn_pipe<<<gattn, 256, ATTN_SMEM>>>(mask, out);
}

// round 13
// speedup vs baseline: 1.1057x; 1.1057x over previous
#include <cuda_runtime.h>
#include <cuda_fp16.h>
#include <math.h>
#include <stdint.h>

#define BB 4
#define LQ 2048
#define LK 2048
#define DM 1024
#define NH 16
#define DK 64
#define NEGV -1000000000.0f

// Pre-split fp16 hi/lo projected tensors: [B*LEN, NH*DK]
__device__ __half g_qh[BB * LQ * NH * DK];
__device__ __half g_ql[BB * LQ * NH * DK];   // written by proj, unused by attn (Q 2-term cut)
__device__ __half g_kh[BB * LK * NH * DK];
__device__ __half g_kl[BB * LK * NH * DK];
__device__ __half g_vh[BB * LK * NH * DK];
__device__ __half g_vl[BB * LK * NH * DK];

__device__ __forceinline__ uint32_t smem_u32(const void* p) {
    uint32_t a;
    asm("{ .reg .u64 t; cvta.to.shared.u64 t, %1; cvt.u32.u64 %0, t; }"
        : "=r"(a) : "l"(p));
    return a;
}
__device__ __forceinline__ void ldm4(unsigned r[4], uint32_t a) {
    asm volatile("ldmatrix.sync.aligned.m8n8.x4.shared.b16 {%0,%1,%2,%3}, [%4];"
        : "=r"(r[0]), "=r"(r[1]), "=r"(r[2]), "=r"(r[3]) : "r"(a));
}
__device__ __forceinline__ void ldm4t(unsigned r[4], uint32_t a) {
    asm volatile("ldmatrix.sync.aligned.m8n8.x4.trans.shared.b16 {%0,%1,%2,%3}, [%4];"
        : "=r"(r[0]), "=r"(r[1]), "=r"(r[2]), "=r"(r[3]) : "r"(a));
}
__device__ __forceinline__ void mma16(float c[4], const unsigned a[4],
                                      unsigned b0, unsigned b1) {
    asm volatile(
        "mma.sync.aligned.m16n8k16.row.col.f32.f16.f16.f32 "
        "{%0,%1,%2,%3},{%4,%5,%6,%7},{%8,%9},{%0,%1,%2,%3};"
        : "+f"(c[0]), "+f"(c[1]), "+f"(c[2]), "+f"(c[3])
        : "r"(a[0]), "r"(a[1]), "r"(a[2]), "r"(a[3]), "r"(b0), "r"(b1));
}
__device__ __forceinline__ void split2x(float a, float b, uint32_t& hi, uint32_t& lo) {
    __half2 h = __floats2half2_rn(a, b);
    float2 hf = __half22float2(h);
    __half2 l = __floats2half2_rn(a - hf.x, b - hf.y);
    hi = *(uint32_t*)&h;
    lo = *(uint32_t*)&l;
}
__device__ __forceinline__ uint32_t pack_h2(float a, float b) {
    __half2 h = __floats2half2_rn(a, b);
    return *(uint32_t*)&h;
}
#define CP16(dst, src) \
    asm volatile("cp.async.cg.shared.global [%0], [%1], 16;" \
                 :: "r"(dst), "l"(src) : "memory")
#define CPCOMMIT() asm volatile("cp.async.commit_group;" ::: "memory")
#define CPWAIT0()  asm volatile("cp.async.wait_group 0;" ::: "memory")
#define CPWAIT1()  asm volatile("cp.async.wait_group 1;" ::: "memory")

// ---------------------------------------------------------------------------
// Fused projections (R8/R11-proven inline version). z = 0:Q scaled by
// log2(e)/8, 1:K, 2:V. BM=128 BN=64 BK=32, 3-term HMMA.
// ---------------------------------------------------------------------------
__global__ __launch_bounds__(256, 2) void proj_hmma(
    const float* __restrict__ Qin, const float* __restrict__ Kin,
    const float* __restrict__ Vin,
    const float* __restrict__ Wq, const float* __restrict__ bq,
    const float* __restrict__ Wk,
    const float* __restrict__ Wv, const float* __restrict__ bv)
{
    const float *A, *W, *bias;
    __half *Ch, *Cl;
    float scale;
    if (blockIdx.z == 0)      { A = Qin; W = Wq; bias = bq;      Ch = g_qh; Cl = g_ql;
                                scale = 0.18033688f; }   // (1/8)*log2(e)
    else if (blockIdx.z == 1) { A = Kin; W = Wk; bias = nullptr; Ch = g_kh; Cl = g_kl; scale = 1.f; }
    else                      { A = Vin; W = Wv; bias = bv;      Ch = g_vh; Cl = g_vl; scale = 1.f; }

    __shared__ __half Ah[128][40], Al[128][40];
    __shared__ __half Wh[64][40],  Wl[64][40];

    const int tid = threadIdx.x, warp = tid >> 5, lane = tid & 31;
    const int g = lane >> 2, tg = lane & 3;
    const int wm = warp & 3, wn = warp >> 2;
    const int bm = blockIdx.y * 128, bn = blockIdx.x * 64;

    const uint32_t ah_b = smem_u32(Ah), al_b = smem_u32(Al);
    const uint32_t wh_b = smem_u32(Wh), wl_b = smem_u32(Wl);
    const int lrow = lane & 15, lcol8 = (lane >> 4) << 3;

    float acc[2][4][4];
#pragma unroll
    for (int i = 0; i < 2; ++i)
#pragma unroll
        for (int j = 0; j < 4; ++j)
#pragma unroll
            for (int t = 0; t < 4; ++t) acc[i][j][t] = 0.f;

    for (int k0 = 0; k0 < DM; k0 += 32) {
        __syncthreads();
#pragma unroll
        for (int i = 0; i < 4; ++i) {            // A: 128x32
            int f4 = tid + i * 256;
            int r = f4 >> 3, c4 = (f4 & 7) * 4;
            float4 v = *(const float4*)(A + (size_t)(bm + r) * DM + k0 + c4);
            uint32_t h0, l0, h1, l1;
            split2x(v.x, v.y, h0, l0);
            split2x(v.z, v.w, h1, l1);
            *(uint32_t*)&Ah[r][c4] = h0; *(uint32_t*)&Ah[r][c4 + 2] = h1;
            *(uint32_t*)&Al[r][c4] = l0; *(uint32_t*)&Al[r][c4 + 2] = l1;
        }
#pragma unroll
        for (int i = 0; i < 2; ++i) {            // W: 64x32
            int f4 = tid + i * 256;
            int r = f4 >> 3, c4 = (f4 & 7) * 4;
            float4 v = *(const float4*)(W + (size_t)(bn + r) * DM + k0 + c4);
            uint32_t h0, l0, h1, l1;
            split2x(v.x, v.y, h0, l0);
            split2x(v.z, v.w, h1, l1);
            *(uint32_t*)&Wh[r][c4] = h0; *(uint32_t*)&Wh[r][c4 + 2] = h1;
            *(uint32_t*)&Wl[r][c4] = l0; *(uint32_t*)&Wl[r][c4 + 2] = l1;
        }
        __syncthreads();

#pragma unroll
        for (int kk = 0; kk < 32; kk += 16) {
            unsigned a_h[2][4], a_l[2][4], b_h[2][4], b_l[2][4];
#pragma unroll
            for (int mf = 0; mf < 2; ++mf) {
                uint32_t off = (uint32_t)((wm * 32 + mf * 16 + lrow) * 40 + kk + lcol8) * 2;
                ldm4(a_h[mf], ah_b + off);
                ldm4(a_l[mf], al_b + off);
            }
#pragma unroll
            for (int nh = 0; nh < 2; ++nh) {
                uint32_t off = (uint32_t)((wn * 32 + nh * 16 + lrow) * 40 + kk + lcol8) * 2;
                ldm4(b_h[nh], wh_b + off);
                ldm4(b_l[nh], wl_b + off);
            }
#pragma unroll
            for (int mf = 0; mf < 2; ++mf)
#pragma unroll
                for (int nh = 0; nh < 2; ++nh)
#pragma unroll
                    for (int j = 0; j < 2; ++j) {
                        int nf = nh * 2 + j;
                        mma16(acc[mf][nf], a_h[mf], b_h[nh][j], b_h[nh][2 + j]);
                        mma16(acc[mf][nf], a_l[mf], b_h[nh][j], b_h[nh][2 + j]);
                        mma16(acc[mf][nf], a_h[mf], b_l[nh][j], b_l[nh][2 + j]);
                    }
        }
    }

#pragma unroll
    for (int mf = 0; mf < 2; ++mf)
#pragma unroll
        for (int nf = 0; nf < 4; ++nf) {
            int r = bm + wm * 32 + mf * 16 + g;
            int c = bn + wn * 32 + (nf >> 1) * 16 + (nf & 1) * 8 + 2 * tg;
            float b0 = 0.f, b1 = 0.f;
            if (bias) { float2 bb = *(const float2*)(bias + c); b0 = bb.x; b1 = bb.y; }
            uint32_t hi, lo;
            split2x((acc[mf][nf][0] + b0) * scale, (acc[mf][nf][1] + b1) * scale, hi, lo);
            *(uint32_t*)(Ch + (size_t)r * (NH * DK) + c) = hi;
            *(uint32_t*)(Cl + (size_t)r * (NH * DK) + c) = lo;
            split2x((acc[mf][nf][2] + b0) * scale, (acc[mf][nf][3] + b1) * scale, hi, lo);
            *(uint32_t*)(Ch + (size_t)(r + 8) * (NH * DK) + c) = hi;
            *(uint32_t*)(Cl + (size_t)(r + 8) * (NH * DK) + c) = lo;
        }
}

// ---------------------------------------------------------------------------
// Flash attention, cross-tile pipeline; Q plain fp16 (2-term S = Qh*(Kh+Kl)),
// PV 2-term. 3 KV buffers, exp2-domain softmax.
// smem layout (halves): QH 0..9216, KH0 @9216 (+3x2304), KL0 @16128,
//                       VH0 @23040, VL0 @29952; MBW @ byte 73728.
// ---------------------------------------------------------------------------
#define ATTN_SMEM 73760
#define BUFB 4608   // bytes per KV buffer step (2304 halves)

__global__ __launch_bounds__(256, 2) void attn_pipe(
    const int* __restrict__ mask, float* __restrict__ out)
{
    extern __shared__ __half sm[];
    const uint32_t smb = smem_u32(sm);
    const uint32_t qh_base = smb;
    const uint32_t kh0 = smb + 9216 * 2;
    const uint32_t kl0 = smb + 16128 * 2;
    const uint32_t vh0 = smb + 23040 * 2;
    const uint32_t vl0 = smb + 29952 * 2;
    uint32_t* MBW = (uint32_t*)((char*)sm + 73728);

    const int tid = threadIdx.x, warp = tid >> 5, lane = tid & 31;
    const int g = lane >> 2, tg = lane & 3;
    const int b = blockIdx.z, h = blockIdx.y;
    const int q0 = blockIdx.x * 128;

    const int lrow = lane & 15, lcol8 = (lane >> 4) << 3;
    const int kvr  = (lane & 7) + ((lane >> 4) << 3);
    const int dcol = ((lane >> 3) & 1) * 8;
    const int cr = tid >> 3, cc = (tid & 7) * 8;
    const uint32_t cpo = (uint32_t)(cr * 72 + cc) * 2;

    float o[8][4];
#pragma unroll
    for (int i = 0; i < 8; ++i)
#pragma unroll
        for (int j = 0; j < 4; ++j) o[i][j] = 0.f;
    float mrA = -INFINITY, mrB = -INFINITY, lrA = 0.f, lrB = 0.f;
    float sa[4][4], sa_n[4][4];

    // ---- prologue: stage Q(hi) + KV tiles 0,1; masks 0,1 ----
    {
        int qrow = tid >> 1, qcb = (tid & 1) * 32;
        size_t qg = (size_t)(b * LQ + q0 + qrow) * (NH * DK) + h * DK + qcb;
        uint32_t qdh = qh_base + (uint32_t)(qrow * 72 + qcb) * 2;
#pragma unroll
        for (int j = 0; j < 4; ++j)
            CP16(qdh + j * 16, g_qh + qg + j * 8);
        size_t g0 = (size_t)(b * LK + cr) * (NH * DK) + h * DK + cc;
        CP16(kh0 + cpo, g_kh + g0); CP16(kl0 + cpo, g_kl + g0);
        CP16(vh0 + cpo, g_vh + g0); CP16(vl0 + cpo, g_vl + g0);
        size_t g1 = (size_t)(b * LK + 32 + cr) * (NH * DK) + h * DK + cc;
        CP16(kh0 + BUFB + cpo, g_kh + g1); CP16(kl0 + BUFB + cpo, g_kl + g1);
        CP16(vh0 + BUFB + cpo, g_vh + g1); CP16(vl0 + BUFB + cpo, g_vl + g1);
        CPCOMMIT();
        if (warp == 0) {
            uint32_t b0 = __ballot_sync(0xffffffffu, mask[b * LK + lane] != 0);
            uint32_t b1 = __ballot_sync(0xffffffffu, mask[b * LK + 32 + lane] != 0);
            if (lane == 0) { MBW[0] = b0; MBW[1] = b1; }
        }
        CPWAIT0();
        __syncthreads();
    }

// S-MMAs: DST = Qh*(Kh + Kl) from buffer BIDX (2-term).
#define S_MMA(DST, BIDX) do {                                                 \
    _Pragma("unroll")                                                         \
    for (int nf = 0; nf < 4; ++nf)                                            \
        { DST[nf][0]=0.f; DST[nf][1]=0.f; DST[nf][2]=0.f; DST[nf][3]=0.f; }   \
    _Pragma("unroll")                                                         \
    for (int kk = 0; kk < 4; ++kk) {                                          \
        unsigned qa_h[4];                                                     \
        uint32_t qoff = (uint32_t)((warp * 16 + lrow) * 72 + kk * 16 + lcol8) * 2; \
        ldm4(qa_h, qh_base + qoff);                                           \
        _Pragma("unroll")                                                     \
        for (int nh = 0; nh < 2; ++nh) {                                      \
            unsigned kbh[4], kbl[4];                                          \
            uint32_t koff = (uint32_t)((nh * 16 + lrow) * 72 + kk * 16 + lcol8) * 2; \
            ldm4(kbh, kh0 + (BIDX) * BUFB + koff);                            \
            ldm4(kbl, kl0 + (BIDX) * BUFB + koff);                            \
            _Pragma("unroll")                                                 \
            for (int j = 0; j < 2; ++j) {                                     \
                int nf = nh * 2 + j;                                          \
                mma16(DST[nf], qa_h, kbh[j], kbh[2 + j]);                     \
                mma16(DST[nf], qa_h, kbl[j], kbl[2 + j]);                     \
            }                                                                 \
        }                                                                     \
    }                                                                         \
} while (0)

#define SOFTMAX_PV(BIDX) do {                                                 \
    const uint32_t mb = MBW[BIDX];                                            \
    float mA = NEGV, mBv = NEGV;                                              \
    _Pragma("unroll")                                                         \
    for (int nf = 0; nf < 4; ++nf) {                                          \
        int c0 = nf * 8 + 2 * tg;                                             \
        bool k0 = (mb >> c0) & 1u;                                            \
        bool k1 = (mb >> (c0 + 1)) & 1u;                                      \
        sa[nf][0] = k0 ? sa[nf][0] : NEGV;                                    \
        sa[nf][1] = k1 ? sa[nf][1] : NEGV;                                    \
        sa[nf][2] = k0 ? sa[nf][2] : NEGV;                                    \
        sa[nf][3] = k1 ? sa[nf][3] : NEGV;                                    \
        mA = fmaxf(mA, fmaxf(sa[nf][0], sa[nf][1]));                          \
        mBv = fmaxf(mBv, fmaxf(sa[nf][2], sa[nf][3]));                        \
    }                                                                         \
    mA = fmaxf(mA, __shfl_xor_sync(0xffffffffu, mA, 1));                      \
    mA = fmaxf(mA, __shfl_xor_sync(0xffffffffu, mA, 2));                      \
    mBv = fmaxf(mBv, __shfl_xor_sync(0xffffffffu, mBv, 1));                   \
    mBv = fmaxf(mBv, __shfl_xor_sync(0xffffffffu, mBv, 2));                   \
    float mnA = fmaxf(mrA, mA), mnB = fmaxf(mrB, mBv);                        \
    float alA = exp2f(mrA - mnA), alB = exp2f(mrB - mnB);                     \
    mrA = mnA; mrB = mnB;                                                     \
    unsigned pah[2][4];                                                       \
    float lsA = 0.f, lsB = 0.f;                                               \
    _Pragma("unroll")                                                         \
    for (int jk = 0; jk < 2; ++jk) {                                          \
        _Pragma("unroll")                                                     \
        for (int t2 = 0; t2 < 2; ++t2) {                                      \
            int nf = jk * 2 + t2;                                             \
            float p0 = exp2f(sa[nf][0] - mnA);                                \
            float p1 = exp2f(sa[nf][1] - mnA);                                \
            float p2 = exp2f(sa[nf][2] - mnB);                                \
            float p3 = exp2f(sa[nf][3] - mnB);                                \
            lsA += p0 + p1; lsB += p2 + p3;                                   \
            pah[jk][2 * t2]     = pack_h2(p0, p1);                            \
            pah[jk][2 * t2 + 1] = pack_h2(p2, p3);                            \
        }                                                                     \
    }                                                                         \
    lsA += __shfl_xor_sync(0xffffffffu, lsA, 1);                              \
    lsA += __shfl_xor_sync(0xffffffffu, lsA, 2);                              \
    lsB += __shfl_xor_sync(0xffffffffu, lsB, 1);                              \
    lsB += __shfl_xor_sync(0xffffffffu, lsB, 2);                              \
    lrA = lrA * alA + lsA;                                                    \
    lrB = lrB * alB + lsB;                                                    \
    _Pragma("unroll")                                                         \
    for (int nf = 0; nf < 8; ++nf) {                                          \
        o[nf][0] *= alA; o[nf][1] *= alA;                                     \
        o[nf][2] *= alB; o[nf][3] *= alB;                                     \
    }                                                                         \
    _Pragma("unroll")                                                         \
    for (int jk = 0; jk < 2; ++jk) {                                          \
        _Pragma("unroll")                                                     \
        for (int dh = 0; dh < 4; ++dh) {                                      \
            unsigned vbh[4], vbl[4];                                          \
            uint32_t voff = (uint32_t)((jk * 16 + kvr) * 72 + dh * 16 + dcol) * 2; \
            ldm4t(vbh, vh0 + (BIDX) * BUFB + voff);                           \
            ldm4t(vbl, vl0 + (BIDX) * BUFB + voff);                           \
            _Pragma("unroll")                                                 \
            for (int j = 0; j < 2; ++j) {                                     \
                int nf = dh * 2 + j;                                          \
                mma16(o[nf], pah[jk], vbh[j], vbh[2 + j]);                    \
                mma16(o[nf], pah[jk], vbl[j], vbl[2 + j]);                    \
            }                                                                 \
        }                                                                     \
    }                                                                         \
} while (0)

#define ITER(T, B, B1, B2) do {                                               \
    __syncthreads();                                                          \
    if ((T) + 2 < 64) {                                                       \
        int ktt = ((T) + 2) * 32;                                             \
        size_t goff = (size_t)(b * LK + ktt + cr) * (NH * DK) + h * DK + cc;  \
        CP16(kh0 + (B2) * BUFB + cpo, g_kh + goff);                           \
        CP16(kl0 + (B2) * BUFB + cpo, g_kl + goff);                           \
        CP16(vh0 + (B2) * BUFB + cpo, g_vh + goff);                           \
        CP16(vl0 + (B2) * BUFB + cpo, g_vl + goff);                           \
        if (warp == 0) {                                                      \
            uint32_t bal = __ballot_sync(0xffffffffu,                         \
                                mask[b * LK + ktt + lane] != 0);              \
            if (lane == 0) MBW[B2] = bal;                                     \
        }                                                                     \
    }                                                                         \
    CPCOMMIT();                                                               \
    CPWAIT1();                                                                \
    __syncthreads();                                                          \
    S_MMA(sa_n, B1);                                                          \
    SOFTMAX_PV(B);                                                            \
    _Pragma("unroll")                                                         \
    for (int nf = 0; nf < 4; ++nf) {                                          \
        sa[nf][0] = sa_n[nf][0]; sa[nf][1] = sa_n[nf][1];                     \
        sa[nf][2] = sa_n[nf][2]; sa[nf][3] = sa_n[nf][3];                     \
    }                                                                         \
} while (0)

    S_MMA(sa, 0);

    int t = 0;
#pragma unroll 1
    for (int i = 0; i < 21; ++i) {
        ITER(t, 0, 1, 2); ++t;
        ITER(t, 1, 2, 0); ++t;
        ITER(t, 2, 0, 1); ++t;
    }
    SOFTMAX_PV(0);

#undef ITER
#undef SOFTMAX_PV
#undef S_MMA

    {
        float iA = 1.f / lrA, iB = 1.f / lrB;
        float* o0 = out + (size_t)(b * LQ + q0 + warp * 16 + g) * (NH * DK) + h * DK;
        float* o1 = o0 + (size_t)8 * (NH * DK);
#pragma unroll
        for (int nf = 0; nf < 8; ++nf) {
            int c = (nf >> 1) * 16 + (nf & 1) * 8 + 2 * tg;
            *(float2*)(o0 + c) = make_float2(o[nf][0] * iA, o[nf][1] * iA);
            *(float2*)(o1 + c) = make_float2(o[nf][2] * iB, o[nf][3] * iB);
        }
    }
}

// ---------------------------------------------------------------------------
extern "C" void kernel_launch(void* const* d_in, const int* in_sizes, int n_in,
                              void* d_out, int out_size)
{
    const float* Q    = (const float*)d_in[0];
    const float* K    = (const float*)d_in[1];
    const float* V    = (const float*)d_in[2];
    const int*   mask = (const int*)d_in[3];
    const float* Wq   = (const float*)d_in[4];
    const float* bq   = (const float*)d_in[5];
    const float* Wk   = (const float*)d_in[6];
    const float* Wv   = (const float*)d_in[7];
    const float* bv   = (const float*)d_in[8];
    float* out = (float*)d_out;

    cudaFuncSetAttribute(attn_pipe, cudaFuncAttributeMaxDynamicSharedMemorySize,
                         ATTN_SMEM);

    dim3 gproj((NH * DK) / 64, (BB * LQ) / 128, 3);  // (16, 64, 3)
    proj_hmma<<<gproj, 256>>>(Q, K, V, Wq, bq, Wk, Wv, bv);

    dim3 gattn(LQ / 128, NH, BB);  // (16, 16, 4)
    attn_pipe<<<gattn, 256, ATTN_SMEM>>>(mask, out);
}

// round 14
// speedup vs baseline: 1.3041x; 1.1794x over previous
#include <cuda_runtime.h>
#include <cuda_fp16.h>
#include <math.h>
#include <stdint.h>

#define BB 4
#define LQ 2048
#define LK 2048
#define DM 1024
#define NH 16
#define DK 64
#define NEGV -1000000000.0f

// Projected q/k/v, plain fp16 (Q pre-scaled by log2(e)/8): [B*LEN, NH*DK]
__device__ __half g_q[BB * LQ * NH * DK];
__device__ __half g_k[BB * LK * NH * DK];
__device__ __half g_v[BB * LK * NH * DK];

__device__ __forceinline__ uint32_t smem_u32(const void* p) {
    uint32_t a;
    asm("{ .reg .u64 t; cvta.to.shared.u64 t, %1; cvt.u32.u64 %0, t; }"
        : "=r"(a) : "l"(p));
    return a;
}
__device__ __forceinline__ void ldm4(unsigned r[4], uint32_t a) {
    asm volatile("ldmatrix.sync.aligned.m8n8.x4.shared.b16 {%0,%1,%2,%3}, [%4];"
        : "=r"(r[0]), "=r"(r[1]), "=r"(r[2]), "=r"(r[3]) : "r"(a));
}
__device__ __forceinline__ void ldm4t(unsigned r[4], uint32_t a) {
    asm volatile("ldmatrix.sync.aligned.m8n8.x4.trans.shared.b16 {%0,%1,%2,%3}, [%4];"
        : "=r"(r[0]), "=r"(r[1]), "=r"(r[2]), "=r"(r[3]) : "r"(a));
}
__device__ __forceinline__ void mma16(float c[4], const unsigned a[4],
                                      unsigned b0, unsigned b1) {
    asm volatile(
        "mma.sync.aligned.m16n8k16.row.col.f32.f16.f16.f32 "
        "{%0,%1,%2,%3},{%4,%5,%6,%7},{%8,%9},{%0,%1,%2,%3};"
        : "+f"(c[0]), "+f"(c[1]), "+f"(c[2]), "+f"(c[3])
        : "r"(a[0]), "r"(a[1]), "r"(a[2]), "r"(a[3]), "r"(b0), "r"(b1));
}
__device__ __forceinline__ void split2x(float a, float b, uint32_t& hi, uint32_t& lo) {
    __half2 h = __floats2half2_rn(a, b);
    float2 hf = __half22float2(h);
    __half2 l = __floats2half2_rn(a - hf.x, b - hf.y);
    hi = *(uint32_t*)&h;
    lo = *(uint32_t*)&l;
}
__device__ __forceinline__ uint32_t pack_h2(float a, float b) {
    __half2 h = __floats2half2_rn(a, b);
    return *(uint32_t*)&h;
}
#define CP16(dst, src) \
    asm volatile("cp.async.cg.shared.global [%0], [%1], 16;" \
                 :: "r"(dst), "l"(src) : "memory")
#define CPCOMMIT() asm volatile("cp.async.commit_group;" ::: "memory")
#define CPWAIT0()  asm volatile("cp.async.wait_group 0;" ::: "memory")
#define CPWAIT1()  asm volatile("cp.async.wait_group 1;" ::: "memory")

// ---------------------------------------------------------------------------
// Fused projections (proven inline version). z = 0:Q scaled by log2(e)/8,
// 1:K, 2:V. BM=128 BN=64 BK=32, 3-term HMMA. Epilogue stores plain fp16.
// ---------------------------------------------------------------------------
__global__ __launch_bounds__(256, 2) void proj_hmma(
    const float* __restrict__ Qin, const float* __restrict__ Kin,
    const float* __restrict__ Vin,
    const float* __restrict__ Wq, const float* __restrict__ bq,
    const float* __restrict__ Wk,
    const float* __restrict__ Wv, const float* __restrict__ bv)
{
    const float *A, *W, *bias;
    __half *C;
    float scale;
    if (blockIdx.z == 0)      { A = Qin; W = Wq; bias = bq;      C = g_q;
                                scale = 0.18033688f; }   // (1/8)*log2(e)
    else if (blockIdx.z == 1) { A = Kin; W = Wk; bias = nullptr; C = g_k; scale = 1.f; }
    else                      { A = Vin; W = Wv; bias = bv;      C = g_v; scale = 1.f; }

    __shared__ __half Ah[128][40], Al[128][40];
    __shared__ __half Wh[64][40],  Wl[64][40];

    const int tid = threadIdx.x, warp = tid >> 5, lane = tid & 31;
    const int g = lane >> 2, tg = lane & 3;
    const int wm = warp & 3, wn = warp >> 2;
    const int bm = blockIdx.y * 128, bn = blockIdx.x * 64;

    const uint32_t ah_b = smem_u32(Ah), al_b = smem_u32(Al);
    const uint32_t wh_b = smem_u32(Wh), wl_b = smem_u32(Wl);
    const int lrow = lane & 15, lcol8 = (lane >> 4) << 3;

    float acc[2][4][4];
#pragma unroll
    for (int i = 0; i < 2; ++i)
#pragma unroll
        for (int j = 0; j < 4; ++j)
#pragma unroll
            for (int t = 0; t < 4; ++t) acc[i][j][t] = 0.f;

    for (int k0 = 0; k0 < DM; k0 += 32) {
        __syncthreads();
#pragma unroll
        for (int i = 0; i < 4; ++i) {            // A: 128x32
            int f4 = tid + i * 256;
            int r = f4 >> 3, c4 = (f4 & 7) * 4;
            float4 v = *(const float4*)(A + (size_t)(bm + r) * DM + k0 + c4);
            uint32_t h0, l0, h1, l1;
            split2x(v.x, v.y, h0, l0);
            split2x(v.z, v.w, h1, l1);
            *(uint32_t*)&Ah[r][c4] = h0; *(uint32_t*)&Ah[r][c4 + 2] = h1;
            *(uint32_t*)&Al[r][c4] = l0; *(uint32_t*)&Al[r][c4 + 2] = l1;
        }
#pragma unroll
        for (int i = 0; i < 2; ++i) {            // W: 64x32
            int f4 = tid + i * 256;
            int r = f4 >> 3, c4 = (f4 & 7) * 4;
            float4 v = *(const float4*)(W + (size_t)(bn + r) * DM + k0 + c4);
            uint32_t h0, l0, h1, l1;
            split2x(v.x, v.y, h0, l0);
            split2x(v.z, v.w, h1, l1);
            *(uint32_t*)&Wh[r][c4] = h0; *(uint32_t*)&Wh[r][c4 + 2] = h1;
            *(uint32_t*)&Wl[r][c4] = l0; *(uint32_t*)&Wl[r][c4 + 2] = l1;
        }
        __syncthreads();

#pragma unroll
        for (int kk = 0; kk < 32; kk += 16) {
            unsigned a_h[2][4], a_l[2][4], b_h[2][4], b_l[2][4];
#pragma unroll
            for (int mf = 0; mf < 2; ++mf) {
                uint32_t off = (uint32_t)((wm * 32 + mf * 16 + lrow) * 40 + kk + lcol8) * 2;
                ldm4(a_h[mf], ah_b + off);
                ldm4(a_l[mf], al_b + off);
            }
#pragma unroll
            for (int nh = 0; nh < 2; ++nh) {
                uint32_t off = (uint32_t)((wn * 32 + nh * 16 + lrow) * 40 + kk + lcol8) * 2;
                ldm4(b_h[nh], wh_b + off);
                ldm4(b_l[nh], wl_b + off);
            }
#pragma unroll
            for (int mf = 0; mf < 2; ++mf)
#pragma unroll
                for (int nh = 0; nh < 2; ++nh)
#pragma unroll
                    for (int j = 0; j < 2; ++j) {
                        int nf = nh * 2 + j;
                        mma16(acc[mf][nf], a_h[mf], b_h[nh][j], b_h[nh][2 + j]);
                        mma16(acc[mf][nf], a_l[mf], b_h[nh][j], b_h[nh][2 + j]);
                        mma16(acc[mf][nf], a_h[mf], b_l[nh][j], b_l[nh][2 + j]);
                    }
        }
    }

#pragma unroll
    for (int mf = 0; mf < 2; ++mf)
#pragma unroll
        for (int nf = 0; nf < 4; ++nf) {
            int r = bm + wm * 32 + mf * 16 + g;
            int c = bn + wn * 32 + (nf >> 1) * 16 + (nf & 1) * 8 + 2 * tg;
            float b0 = 0.f, b1 = 0.f;
            if (bias) { float2 bb = *(const float2*)(bias + c); b0 = bb.x; b1 = bb.y; }
            *(uint32_t*)(C + (size_t)r * (NH * DK) + c) =
                pack_h2((acc[mf][nf][0] + b0) * scale, (acc[mf][nf][1] + b1) * scale);
            *(uint32_t*)(C + (size_t)(r + 8) * (NH * DK) + c) =
                pack_h2((acc[mf][nf][2] + b0) * scale, (acc[mf][nf][3] + b1) * scale);
        }
}

// ---------------------------------------------------------------------------
// Flash attention, plain fp16 q/k/v (S = Q*K, PV = P*V, single term each),
// cross-tile pipeline, 3 KV buffers, exp2-domain softmax.
// smem (halves): QH 0..9216, KH0 @9216 (+3x2304), VH0 @16128 (+3x2304);
// MBW @ byte 46080. Total 46112 B.
// ---------------------------------------------------------------------------
#define ATTN_SMEM 46112
#define BUFB 4608   // bytes per KV buffer step (2304 halves)

__global__ __launch_bounds__(256, 2) void attn_pipe(
    const int* __restrict__ mask, float* __restrict__ out)
{
    extern __shared__ __half sm[];
    const uint32_t smb = smem_u32(sm);
    const uint32_t qh_base = smb;
    const uint32_t kh0 = smb + 9216 * 2;
    const uint32_t vh0 = smb + 16128 * 2;
    uint32_t* MBW = (uint32_t*)((char*)sm + 46080);

    const int tid = threadIdx.x, warp = tid >> 5, lane = tid & 31;
    const int g = lane >> 2, tg = lane & 3;
    const int b = blockIdx.z, h = blockIdx.y;
    const int q0 = blockIdx.x * 128;

    const int lrow = lane & 15, lcol8 = (lane >> 4) << 3;
    const int kvr  = (lane & 7) + ((lane >> 4) << 3);
    const int dcol = ((lane >> 3) & 1) * 8;
    const int cr = tid >> 3, cc = (tid & 7) * 8;
    const uint32_t cpo = (uint32_t)(cr * 72 + cc) * 2;

    float o[8][4];
#pragma unroll
    for (int i = 0; i < 8; ++i)
#pragma unroll
        for (int j = 0; j < 4; ++j) o[i][j] = 0.f;
    float mrA = -INFINITY, mrB = -INFINITY, lrA = 0.f, lrB = 0.f;
    float sa[4][4], sa_n[4][4];

    // ---- prologue: stage Q + KV tiles 0,1; masks 0,1 ----
    {
        int qrow = tid >> 1, qcb = (tid & 1) * 32;
        size_t qg = (size_t)(b * LQ + q0 + qrow) * (NH * DK) + h * DK + qcb;
        uint32_t qdh = qh_base + (uint32_t)(qrow * 72 + qcb) * 2;
#pragma unroll
        for (int j = 0; j < 4; ++j)
            CP16(qdh + j * 16, g_q + qg + j * 8);
        size_t g0 = (size_t)(b * LK + cr) * (NH * DK) + h * DK + cc;
        CP16(kh0 + cpo, g_k + g0);
        CP16(vh0 + cpo, g_v + g0);
        size_t g1 = (size_t)(b * LK + 32 + cr) * (NH * DK) + h * DK + cc;
        CP16(kh0 + BUFB + cpo, g_k + g1);
        CP16(vh0 + BUFB + cpo, g_v + g1);
        CPCOMMIT();
        if (warp == 0) {
            uint32_t b0 = __ballot_sync(0xffffffffu, mask[b * LK + lane] != 0);
            uint32_t b1 = __ballot_sync(0xffffffffu, mask[b * LK + 32 + lane] != 0);
            if (lane == 0) { MBW[0] = b0; MBW[1] = b1; }
        }
        CPWAIT0();
        __syncthreads();
    }

// S-MMAs: DST = Q*K from buffer BIDX (single term).
#define S_MMA(DST, BIDX) do {                                                 \
    _Pragma("unroll")                                                         \
    for (int nf = 0; nf < 4; ++nf)                                            \
        { DST[nf][0]=0.f; DST[nf][1]=0.f; DST[nf][2]=0.f; DST[nf][3]=0.f; }   \
    _Pragma("unroll")                                                         \
    for (int kk = 0; kk < 4; ++kk) {                                          \
        unsigned qa[4];                                                       \
        uint32_t qoff = (uint32_t)((warp * 16 + lrow) * 72 + kk * 16 + lcol8) * 2; \
        ldm4(qa, qh_base + qoff);                                             \
        _Pragma("unroll")                                                     \
        for (int nh = 0; nh < 2; ++nh) {                                      \
            unsigned kb[4];                                                   \
            uint32_t koff = (uint32_t)((nh * 16 + lrow) * 72 + kk * 16 + lcol8) * 2; \
            ldm4(kb, kh0 + (BIDX) * BUFB + koff);                             \
            mma16(DST[nh * 2 + 0], qa, kb[0], kb[2]);                         \
            mma16(DST[nh * 2 + 1], qa, kb[1], kb[3]);                         \
        }                                                                     \
    }                                                                         \
} while (0)

#define SOFTMAX_PV(BIDX) do {                                                 \
    const uint32_t mb = MBW[BIDX];                                            \
    float mA = NEGV, mBv = NEGV;                                              \
    _Pragma("unroll")                                                         \
    for (int nf = 0; nf < 4; ++nf) {                                          \
        int c0 = nf * 8 + 2 * tg;                                             \
        bool k0 = (mb >> c0) & 1u;                                            \
        bool k1 = (mb >> (c0 + 1)) & 1u;                                      \
        sa[nf][0] = k0 ? sa[nf][0] : NEGV;                                    \
        sa[nf][1] = k1 ? sa[nf][1] : NEGV;                                    \
        sa[nf][2] = k0 ? sa[nf][2] : NEGV;                                    \
        sa[nf][3] = k1 ? sa[nf][3] : NEGV;                                    \
        mA = fmaxf(mA, fmaxf(sa[nf][0], sa[nf][1]));                          \
        mBv = fmaxf(mBv, fmaxf(sa[nf][2], sa[nf][3]));                        \
    }                                                                         \
    mA = fmaxf(mA, __shfl_xor_sync(0xffffffffu, mA, 1));                      \
    mA = fmaxf(mA, __shfl_xor_sync(0xffffffffu, mA, 2));                      \
    mBv = fmaxf(mBv, __shfl_xor_sync(0xffffffffu, mBv, 1));                   \
    mBv = fmaxf(mBv, __shfl_xor_sync(0xffffffffu, mBv, 2));                   \
    float mnA = fmaxf(mrA, mA), mnB = fmaxf(mrB, mBv);                        \
    float alA = exp2f(mrA - mnA), alB = exp2f(mrB - mnB);                     \
    mrA = mnA; mrB = mnB;                                                     \
    unsigned pah[2][4];                                                       \
    float lsA = 0.f, lsB = 0.f;                                               \
    _Pragma("unroll")                                                         \
    for (int jk = 0; jk < 2; ++jk) {                                          \
        _Pragma("unroll")                                                     \
        for (int t2 = 0; t2 < 2; ++t2) {                                      \
            int nf = jk * 2 + t2;                                             \
            float p0 = exp2f(sa[nf][0] - mnA);                                \
            float p1 = exp2f(sa[nf][1] - mnA);                                \
            float p2 = exp2f(sa[nf][2] - mnB);                                \
            float p3 = exp2f(sa[nf][3] - mnB);                                \
            lsA += p0 + p1; lsB += p2 + p3;                                   \
            pah[jk][2 * t2]     = pack_h2(p0, p1);                            \
            pah[jk][2 * t2 + 1] = pack_h2(p2, p3);                            \
        }                                                                     \
    }                                                                         \
    lsA += __shfl_xor_sync(0xffffffffu, lsA, 1);                              \
    lsA += __shfl_xor_sync(0xffffffffu, lsA, 2);                              \
    lsB += __shfl_xor_sync(0xffffffffu, lsB, 1);                              \
    lsB += __shfl_xor_sync(0xffffffffu, lsB, 2);                              \
    lrA = lrA * alA + lsA;                                                    \
    lrB = lrB * alB + lsB;                                                    \
    _Pragma("unroll")                                                         \
    for (int nf = 0; nf < 8; ++nf) {                                          \
        o[nf][0] *= alA; o[nf][1] *= alA;                                     \
        o[nf][2] *= alB; o[nf][3] *= alB;                                     \
    }                                                                         \
    _Pragma("unroll")                                                         \
    for (int jk = 0; jk < 2; ++jk) {                                          \
        _Pragma("unroll")                                                     \
        for (int dh = 0; dh < 4; ++dh) {                                      \
            unsigned vb[4];                                                   \
            uint32_t voff = (uint32_t)((jk * 16 + kvr) * 72 + dh * 16 + dcol) * 2; \
            ldm4t(vb, vh0 + (BIDX) * BUFB + voff);                            \
            mma16(o[dh * 2 + 0], pah[jk], vb[0], vb[2]);                      \
            mma16(o[dh * 2 + 1], pah[jk], vb[1], vb[3]);                      \
        }                                                                     \
    }                                                                         \
} while (0)

#define ITER(T, B, B1, B2) do {                                               \
    __syncthreads();                                                          \
    if ((T) + 2 < 64) {                                                       \
        int ktt = ((T) + 2) * 32;                                             \
        size_t goff = (size_t)(b * LK + ktt + cr) * (NH * DK) + h * DK + cc;  \
        CP16(kh0 + (B2) * BUFB + cpo, g_k + goff);                            \
        CP16(vh0 + (B2) * BUFB + cpo, g_v + goff);                            \
        if (warp == 0) {                                                      \
            uint32_t bal = __ballot_sync(0xffffffffu,                         \
                                mask[b * LK + ktt + lane] != 0);              \
            if (lane == 0) MBW[B2] = bal;                                     \
        }                                                                     \
    }                                                                         \
    CPCOMMIT();                                                               \
    CPWAIT1();                                                                \
    __syncthreads();                                                          \
    S_MMA(sa_n, B1);                                                          \
    SOFTMAX_PV(B);                                                            \
    _Pragma("unroll")                                                         \
    for (int nf = 0; nf < 4; ++nf) {                                          \
        sa[nf][0] = sa_n[nf][0]; sa[nf][1] = sa_n[nf][1];                     \
        sa[nf][2] = sa_n[nf][2]; sa[nf][3] = sa_n[nf][3];                     \
    }                                                                         \
} while (0)

    S_MMA(sa, 0);

    int t = 0;
#pragma unroll 1
    for (int i = 0; i < 21; ++i) {
        ITER(t, 0, 1, 2); ++t;
        ITER(t, 1, 2, 0); ++t;
        ITER(t, 2, 0, 1); ++t;
    }
    SOFTMAX_PV(0);

#undef ITER
#undef SOFTMAX_PV
#undef S_MMA

    {
        float iA = 1.f / lrA, iB = 1.f / lrB;
        float* o0 = out + (size_t)(b * LQ + q0 + warp * 16 + g) * (NH * DK) + h * DK;
        float* o1 = o0 + (size_t)8 * (NH * DK);
#pragma unroll
        for (int nf = 0; nf < 8; ++nf) {
            int c = (nf >> 1) * 16 + (nf & 1) * 8 + 2 * tg;
            *(float2*)(o0 + c) = make_float2(o[nf][0] * iA, o[nf][1] * iA);
            *(float2*)(o1 + c) = make_float2(o[nf][2] * iB, o[nf][3] * iB);
        }
    }
}

// ---------------------------------------------------------------------------
extern "C" void kernel_launch(void* const* d_in, const int* in_sizes, int n_in,
                              void* d_out, int out_size)
{
    const float* Q    = (const float*)d_in[0];
    const float* K    = (const float*)d_in[1];
    const float* V    = (const float*)d_in[2];
    const int*   mask = (const int*)d_in[3];
    const float* Wq   = (const float*)d_in[4];
    const float* bq   = (const float*)d_in[5];
    const float* Wk   = (const float*)d_in[6];
    const float* Wv   = (const float*)d_in[7];
    const float* bv   = (const float*)d_in[8];
    float* out = (float*)d_out;

    cudaFuncSetAttribute(attn_pipe, cudaFuncAttributeMaxDynamicSharedMemorySize,
                         ATTN_SMEM);

    dim3 gproj((NH * DK) / 64, (BB * LQ) / 128, 3);  // (16, 64, 3)
    proj_hmma<<<gproj, 256>>>(Q, K, V, Wq, bq, Wk, Wv, bv);

    dim3 gattn(LQ / 128, NH, BB);  // (16, 16, 4)
    attn_pipe<<<gattn, 256, ATTN_SMEM>>>(mask, out);
}

// round 15
// speedup vs baseline: 1.4840x; 1.1380x over previous
#include <cuda_runtime.h>
#include <cuda_fp16.h>
#include <math.h>
#include <stdint.h>

#define BB 4
#define LQ 2048
#define LK 2048
#define DM 1024
#define NH 16
#define DK 64
#define NEGV -1000000000.0f

// Projected q/k/v, plain fp16 (Q pre-scaled by log2(e)/8): [B*LEN, NH*DK]
__device__ __half g_q[BB * LQ * NH * DK];
__device__ __half g_k[BB * LK * NH * DK];
__device__ __half g_v[BB * LK * NH * DK];

__device__ __forceinline__ uint32_t smem_u32(const void* p) {
    uint32_t a;
    asm("{ .reg .u64 t; cvta.to.shared.u64 t, %1; cvt.u32.u64 %0, t; }"
        : "=r"(a) : "l"(p));
    return a;
}
__device__ __forceinline__ void ldm4(unsigned r[4], uint32_t a) {
    asm volatile("ldmatrix.sync.aligned.m8n8.x4.shared.b16 {%0,%1,%2,%3}, [%4];"
        : "=r"(r[0]), "=r"(r[1]), "=r"(r[2]), "=r"(r[3]) : "r"(a));
}
__device__ __forceinline__ void ldm4t(unsigned r[4], uint32_t a) {
    asm volatile("ldmatrix.sync.aligned.m8n8.x4.trans.shared.b16 {%0,%1,%2,%3}, [%4];"
        : "=r"(r[0]), "=r"(r[1]), "=r"(r[2]), "=r"(r[3]) : "r"(a));
}
__device__ __forceinline__ void mma16(float c[4], const unsigned a[4],
                                      unsigned b0, unsigned b1) {
    asm volatile(
        "mma.sync.aligned.m16n8k16.row.col.f32.f16.f16.f32 "
        "{%0,%1,%2,%3},{%4,%5,%6,%7},{%8,%9},{%0,%1,%2,%3};"
        : "+f"(c[0]), "+f"(c[1]), "+f"(c[2]), "+f"(c[3])
        : "r"(a[0]), "r"(a[1]), "r"(a[2]), "r"(a[3]), "r"(b0), "r"(b1));
}
__device__ __forceinline__ void split2x(float a, float b, uint32_t& hi, uint32_t& lo) {
    __half2 h = __floats2half2_rn(a, b);
    float2 hf = __half22float2(h);
    __half2 l = __floats2half2_rn(a - hf.x, b - hf.y);
    hi = *(uint32_t*)&h;
    lo = *(uint32_t*)&l;
}
__device__ __forceinline__ uint32_t pack_h2(float a, float b) {
    __half2 h = __floats2half2_rn(a, b);
    return *(uint32_t*)&h;
}
#define CP16(dst, src) \
    asm volatile("cp.async.cg.shared.global [%0], [%1], 16;" \
                 :: "r"(dst), "l"(src) : "memory")
#define CPCOMMIT() asm volatile("cp.async.commit_group;" ::: "memory")
#define CPWAIT0()  asm volatile("cp.async.wait_group 0;" ::: "memory")
#define CPWAIT1()  asm volatile("cp.async.wait_group 1;" ::: "memory")

// ---------------------------------------------------------------------------
// Fused projections. z = 0:Q scaled by log2(e)/8, 1:K, 2:V.
// BM=128 BN=64 BK=32. A plain fp16, W 2-term: acc = Ah*Wh + Ah*Wl.
// (A-lo term dropped: consumers round q/k/v to fp16 anyway.)
// ---------------------------------------------------------------------------
__global__ __launch_bounds__(256, 2) void proj_hmma(
    const float* __restrict__ Qin, const float* __restrict__ Kin,
    const float* __restrict__ Vin,
    const float* __restrict__ Wq, const float* __restrict__ bq,
    const float* __restrict__ Wk,
    const float* __restrict__ Wv, const float* __restrict__ bv)
{
    const float *A, *W, *bias;
    __half *C;
    float scale;
    if (blockIdx.z == 0)      { A = Qin; W = Wq; bias = bq;      C = g_q;
                                scale = 0.18033688f; }   // (1/8)*log2(e)
    else if (blockIdx.z == 1) { A = Kin; W = Wk; bias = nullptr; C = g_k; scale = 1.f; }
    else                      { A = Vin; W = Wv; bias = bv;      C = g_v; scale = 1.f; }

    __shared__ __half Ah[128][40];
    __shared__ __half Wh[64][40], Wl[64][40];

    const int tid = threadIdx.x, warp = tid >> 5, lane = tid & 31;
    const int g = lane >> 2, tg = lane & 3;
    const int wm = warp & 3, wn = warp >> 2;
    const int bm = blockIdx.y * 128, bn = blockIdx.x * 64;

    const uint32_t ah_b = smem_u32(Ah);
    const uint32_t wh_b = smem_u32(Wh), wl_b = smem_u32(Wl);
    const int lrow = lane & 15, lcol8 = (lane >> 4) << 3;

    float acc[2][4][4];
#pragma unroll
    for (int i = 0; i < 2; ++i)
#pragma unroll
        for (int j = 0; j < 4; ++j)
#pragma unroll
            for (int t = 0; t < 4; ++t) acc[i][j][t] = 0.f;

    for (int k0 = 0; k0 < DM; k0 += 32) {
        __syncthreads();
#pragma unroll
        for (int i = 0; i < 4; ++i) {            // A: 128x32, plain fp16
            int f4 = tid + i * 256;
            int r = f4 >> 3, c4 = (f4 & 7) * 4;
            float4 v = *(const float4*)(A + (size_t)(bm + r) * DM + k0 + c4);
            *(uint32_t*)&Ah[r][c4]     = pack_h2(v.x, v.y);
            *(uint32_t*)&Ah[r][c4 + 2] = pack_h2(v.z, v.w);
        }
#pragma unroll
        for (int i = 0; i < 2; ++i) {            // W: 64x32, hi/lo
            int f4 = tid + i * 256;
            int r = f4 >> 3, c4 = (f4 & 7) * 4;
            float4 v = *(const float4*)(W + (size_t)(bn + r) * DM + k0 + c4);
            uint32_t h0, l0, h1, l1;
            split2x(v.x, v.y, h0, l0);
            split2x(v.z, v.w, h1, l1);
            *(uint32_t*)&Wh[r][c4] = h0; *(uint32_t*)&Wh[r][c4 + 2] = h1;
            *(uint32_t*)&Wl[r][c4] = l0; *(uint32_t*)&Wl[r][c4 + 2] = l1;
        }
        __syncthreads();

#pragma unroll
        for (int kk = 0; kk < 32; kk += 16) {
            unsigned a_h[2][4], b_h[2][4], b_l[2][4];
#pragma unroll
            for (int mf = 0; mf < 2; ++mf) {
                uint32_t off = (uint32_t)((wm * 32 + mf * 16 + lrow) * 40 + kk + lcol8) * 2;
                ldm4(a_h[mf], ah_b + off);
            }
#pragma unroll
            for (int nh = 0; nh < 2; ++nh) {
                uint32_t off = (uint32_t)((wn * 32 + nh * 16 + lrow) * 40 + kk + lcol8) * 2;
                ldm4(b_h[nh], wh_b + off);
                ldm4(b_l[nh], wl_b + off);
            }
#pragma unroll
            for (int mf = 0; mf < 2; ++mf)
#pragma unroll
                for (int nh = 0; nh < 2; ++nh)
#pragma unroll
                    for (int j = 0; j < 2; ++j) {
                        int nf = nh * 2 + j;
                        mma16(acc[mf][nf], a_h[mf], b_h[nh][j], b_h[nh][2 + j]);
                        mma16(acc[mf][nf], a_h[mf], b_l[nh][j], b_l[nh][2 + j]);
                    }
        }
    }

#pragma unroll
    for (int mf = 0; mf < 2; ++mf)
#pragma unroll
        for (int nf = 0; nf < 4; ++nf) {
            int r = bm + wm * 32 + mf * 16 + g;
            int c = bn + wn * 32 + (nf >> 1) * 16 + (nf & 1) * 8 + 2 * tg;
            float b0 = 0.f, b1 = 0.f;
            if (bias) { float2 bb = *(const float2*)(bias + c); b0 = bb.x; b1 = bb.y; }
            *(uint32_t*)(C + (size_t)r * (NH * DK) + c) =
                pack_h2((acc[mf][nf][0] + b0) * scale, (acc[mf][nf][1] + b1) * scale);
            *(uint32_t*)(C + (size_t)(r + 8) * (NH * DK) + c) =
                pack_h2((acc[mf][nf][2] + b0) * scale, (acc[mf][nf][3] + b1) * scale);
        }
}

// ---------------------------------------------------------------------------
// Flash attention (R14 version, unchanged — proven 333us). Plain fp16 q/k/v,
// cross-tile pipeline, 3 KV buffers, exp2-domain softmax.
// ---------------------------------------------------------------------------
#define ATTN_SMEM 46112
#define BUFB 4608   // bytes per KV buffer step (2304 halves)

__global__ __launch_bounds__(256, 2) void attn_pipe(
    const int* __restrict__ mask, float* __restrict__ out)
{
    extern __shared__ __half sm[];
    const uint32_t smb = smem_u32(sm);
    const uint32_t qh_base = smb;
    const uint32_t kh0 = smb + 9216 * 2;
    const uint32_t vh0 = smb + 16128 * 2;
    uint32_t* MBW = (uint32_t*)((char*)sm + 46080);

    const int tid = threadIdx.x, warp = tid >> 5, lane = tid & 31;
    const int g = lane >> 2, tg = lane & 3;
    const int b = blockIdx.z, h = blockIdx.y;
    const int q0 = blockIdx.x * 128;

    const int lrow = lane & 15, lcol8 = (lane >> 4) << 3;
    const int kvr  = (lane & 7) + ((lane >> 4) << 3);
    const int dcol = ((lane >> 3) & 1) * 8;
    const int cr = tid >> 3, cc = (tid & 7) * 8;
    const uint32_t cpo = (uint32_t)(cr * 72 + cc) * 2;

    float o[8][4];
#pragma unroll
    for (int i = 0; i < 8; ++i)
#pragma unroll
        for (int j = 0; j < 4; ++j) o[i][j] = 0.f;
    float mrA = -INFINITY, mrB = -INFINITY, lrA = 0.f, lrB = 0.f;
    float sa[4][4], sa_n[4][4];

    // ---- prologue: stage Q + KV tiles 0,1; masks 0,1 ----
    {
        int qrow = tid >> 1, qcb = (tid & 1) * 32;
        size_t qg = (size_t)(b * LQ + q0 + qrow) * (NH * DK) + h * DK + qcb;
        uint32_t qdh = qh_base + (uint32_t)(qrow * 72 + qcb) * 2;
#pragma unroll
        for (int j = 0; j < 4; ++j)
            CP16(qdh + j * 16, g_q + qg + j * 8);
        size_t g0 = (size_t)(b * LK + cr) * (NH * DK) + h * DK + cc;
        CP16(kh0 + cpo, g_k + g0);
        CP16(vh0 + cpo, g_v + g0);
        size_t g1 = (size_t)(b * LK + 32 + cr) * (NH * DK) + h * DK + cc;
        CP16(kh0 + BUFB + cpo, g_k + g1);
        CP16(vh0 + BUFB + cpo, g_v + g1);
        CPCOMMIT();
        if (warp == 0) {
            uint32_t b0 = __ballot_sync(0xffffffffu, mask[b * LK + lane] != 0);
            uint32_t b1 = __ballot_sync(0xffffffffu, mask[b * LK + 32 + lane] != 0);
            if (lane == 0) { MBW[0] = b0; MBW[1] = b1; }
        }
        CPWAIT0();
        __syncthreads();
    }

#define S_MMA(DST, BIDX) do {                                                 \
    _Pragma("unroll")                                                         \
    for (int nf = 0; nf < 4; ++nf)                                            \
        { DST[nf][0]=0.f; DST[nf][1]=0.f; DST[nf][2]=0.f; DST[nf][3]=0.f; }   \
    _Pragma("unroll")                                                         \
    for (int kk = 0; kk < 4; ++kk) {                                          \
        unsigned qa[4];                                                       \
        uint32_t qoff = (uint32_t)((warp * 16 + lrow) * 72 + kk * 16 + lcol8) * 2; \
        ldm4(qa, qh_base + qoff);                                             \
        _Pragma("unroll")                                                     \
        for (int nh = 0; nh < 2; ++nh) {                                      \
            unsigned kb[4];                                                   \
            uint32_t koff = (uint32_t)((nh * 16 + lrow) * 72 + kk * 16 + lcol8) * 2; \
            ldm4(kb, kh0 + (BIDX) * BUFB + koff);                             \
            mma16(DST[nh * 2 + 0], qa, kb[0], kb[2]);                         \
            mma16(DST[nh * 2 + 1], qa, kb[1], kb[3]);                         \
        }                                                                     \
    }                                                                         \
} while (0)

#define SOFTMAX_PV(BIDX) do {                                                 \
    const uint32_t mb = MBW[BIDX];                                            \
    float mA = NEGV, mBv = NEGV;                                              \
    _Pragma("unroll")                                                         \
    for (int nf = 0; nf < 4; ++nf) {                                          \
        int c0 = nf * 8 + 2 * tg;                                             \
        bool k0 = (mb >> c0) & 1u;                                            \
        bool k1 = (mb >> (c0 + 1)) & 1u;                                      \
        sa[nf][0] = k0 ? sa[nf][0] : NEGV;                                    \
        sa[nf][1] = k1 ? sa[nf][1] : NEGV;                                    \
        sa[nf][2] = k0 ? sa[nf][2] : NEGV;                                    \
        sa[nf][3] = k1 ? sa[nf][3] : NEGV;                                    \
        mA = fmaxf(mA, fmaxf(sa[nf][0], sa[nf][1]));                          \
        mBv = fmaxf(mBv, fmaxf(sa[nf][2], sa[nf][3]));                        \
    }                                                                         \
    mA = fmaxf(mA, __shfl_xor_sync(0xffffffffu, mA, 1));                      \
    mA = fmaxf(mA, __shfl_xor_sync(0xffffffffu, mA, 2));                      \
    mBv = fmaxf(mBv, __shfl_xor_sync(0xffffffffu, mBv, 1));                   \
    mBv = fmaxf(mBv, __shfl_xor_sync(0xffffffffu, mBv, 2));                   \
    float mnA = fmaxf(mrA, mA), mnB = fmaxf(mrB, mBv);                        \
    float alA = exp2f(mrA - mnA), alB = exp2f(mrB - mnB);                     \
    mrA = mnA; mrB = mnB;                                                     \
    unsigned pah[2][4];                                                       \
    float lsA = 0.f, lsB = 0.f;                                               \
    _Pragma("unroll")                                                         \
    for (int jk = 0; jk < 2; ++jk) {                                          \
        _Pragma("unroll")                                                     \
        for (int t2 = 0; t2 < 2; ++t2) {                                      \
            int nf = jk * 2 + t2;                                             \
            float p0 = exp2f(sa[nf][0] - mnA);                                \
            float p1 = exp2f(sa[nf][1] - mnA);                                \
            float p2 = exp2f(sa[nf][2] - mnB);                                \
            float p3 = exp2f(sa[nf][3] - mnB);                                \
            lsA += p0 + p1; lsB += p2 + p3;                                   \
            pah[jk][2 * t2]     = pack_h2(p0, p1);                            \
            pah[jk][2 * t2 + 1] = pack_h2(p2, p3);                            \
        }                                                                     \
    }                                                                         \
    lsA += __shfl_xor_sync(0xffffffffu, lsA, 1);                              \
    lsA += __shfl_xor_sync(0xffffffffu, lsA, 2);                              \
    lsB += __shfl_xor_sync(0xffffffffu, lsB, 1);                              \
    lsB += __shfl_xor_sync(0xffffffffu, lsB, 2);                              \
    lrA = lrA * alA + lsA;                                                    \
    lrB = lrB * alB + lsB;                                                    \
    _Pragma("unroll")                                                         \
    for (int nf = 0; nf < 8; ++nf) {                                          \
        o[nf][0] *= alA; o[nf][1] *= alA;                                     \
        o[nf][2] *= alB; o[nf][3] *= alB;                                     \
    }                                                                         \
    _Pragma("unroll")                                                         \
    for (int jk = 0; jk < 2; ++jk) {                                          \
        _Pragma("unroll")                                                     \
        for (int dh = 0; dh < 4; ++dh) {                                      \
            unsigned vb[4];                                                   \
            uint32_t voff = (uint32_t)((jk * 16 + kvr) * 72 + dh * 16 + dcol) * 2; \
            ldm4t(vb, vh0 + (BIDX) * BUFB + voff);                            \
            mma16(o[dh * 2 + 0], pah[jk], vb[0], vb[2]);                      \
            mma16(o[dh * 2 + 1], pah[jk], vb[1], vb[3]);                      \
        }                                                                     \
    }                                                                         \
} while (0)

#define ITER(T, B, B1, B2) do {                                               \
    __syncthreads();                                                          \
    if ((T) + 2 < 64) {                                                       \
        int ktt = ((T) + 2) * 32;                                             \
        size_t goff = (size_t)(b * LK + ktt + cr) * (NH * DK) + h * DK + cc;  \
        CP16(kh0 + (B2) * BUFB + cpo, g_k + goff);                            \
        CP16(vh0 + (B2) * BUFB + cpo, g_v + goff);                            \
        if (warp == 0) {                                                      \
            uint32_t bal = __ballot_sync(0xffffffffu,                         \
                                mask[b * LK + ktt + lane] != 0);              \
            if (lane == 0) MBW[B2] = bal;                                     \
        }                                                                     \
    }                                                                         \
    CPCOMMIT();                                                               \
    CPWAIT1();                                                                \
    __syncthreads();                                                          \
    S_MMA(sa_n, B1);                                                          \
    SOFTMAX_PV(B);                                                            \
    _Pragma("unroll")                                                         \
    for (int nf = 0; nf < 4; ++nf) {                                          \
        sa[nf][0] = sa_n[nf][0]; sa[nf][1] = sa_n[nf][1];                     \
        sa[nf][2] = sa_n[nf][2]; sa[nf][3] = sa_n[nf][3];                     \
    }                                                                         \
} while (0)

    S_MMA(sa, 0);

    int t = 0;
#pragma unroll 1
    for (int i = 0; i < 21; ++i) {
        ITER(t, 0, 1, 2); ++t;
        ITER(t, 1, 2, 0); ++t;
        ITER(t, 2, 0, 1); ++t;
    }
    SOFTMAX_PV(0);

#undef ITER
#undef SOFTMAX_PV
#undef S_MMA

    {
        float iA = 1.f / lrA, iB = 1.f / lrB;
        float* o0 = out + (size_t)(b * LQ + q0 + warp * 16 + g) * (NH * DK) + h * DK;
        float* o1 = o0 + (size_t)8 * (NH * DK);
#pragma unroll
        for (int nf = 0; nf < 8; ++nf) {
            int c = (nf >> 1) * 16 + (nf & 1) * 8 + 2 * tg;
            *(float2*)(o0 + c) = make_float2(o[nf][0] * iA, o[nf][1] * iA);
            *(float2*)(o1 + c) = make_float2(o[nf][2] * iB, o[nf][3] * iB);
        }
    }
}

// ---------------------------------------------------------------------------
extern "C" void kernel_launch(void* const* d_in, const int* in_sizes, int n_in,
                              void* d_out, int out_size)
{
    const float* Q    = (const float*)d_in[0];
    const float* K    = (const float*)d_in[1];
    const float* V    = (const float*)d_in[2];
    const int*   mask = (const int*)d_in[3];
    const float* Wq   = (const float*)d_in[4];
    const float* bq   = (const float*)d_in[5];
    const float* Wk   = (const float*)d_in[6];
    const float* Wv   = (const float*)d_in[7];
    const float* bv   = (const float*)d_in[8];
    float* out = (float*)d_out;

    cudaFuncSetAttribute(attn_pipe, cudaFuncAttributeMaxDynamicSharedMemorySize,
                         ATTN_SMEM);

    dim3 gproj((NH * DK) / 64, (BB * LQ) / 128, 3);  // (16, 64, 3)
    proj_hmma<<<gproj, 256>>>(Q, K, V, Wq, bq, Wk, Wv, bv);

    dim3 gattn(LQ / 128, NH, BB);  // (16, 16, 4)
    attn_pipe<<<gattn, 256, ATTN_SMEM>>>(mask, out);
}

// round 16
// speedup vs baseline: 1.6056x; 1.0820x over previous
#include <cuda_runtime.h>
#include <cuda_fp16.h>
#include <math.h>
#include <stdint.h>

#define BB 4
#define LQ 2048
#define LK 2048
#define DM 1024
#define NH 16
#define DK 64
#define NEGV -1000000000.0f

// Projected q/k/v, plain fp16 (Q pre-scaled by log2(e)/8): [B*LEN, NH*DK]
__device__ __half g_q[BB * LQ * NH * DK];
__device__ __half g_k[BB * LK * NH * DK];
__device__ __half g_v[BB * LK * NH * DK];

__device__ __forceinline__ uint32_t smem_u32(const void* p) {
    uint32_t a;
    asm("{ .reg .u64 t; cvta.to.shared.u64 t, %1; cvt.u32.u64 %0, t; }"
        : "=r"(a) : "l"(p));
    return a;
}
__device__ __forceinline__ void ldm4(unsigned r[4], uint32_t a) {
    asm volatile("ldmatrix.sync.aligned.m8n8.x4.shared.b16 {%0,%1,%2,%3}, [%4];"
        : "=r"(r[0]), "=r"(r[1]), "=r"(r[2]), "=r"(r[3]) : "r"(a));
}
__device__ __forceinline__ void ldm4t(unsigned r[4], uint32_t a) {
    asm volatile("ldmatrix.sync.aligned.m8n8.x4.trans.shared.b16 {%0,%1,%2,%3}, [%4];"
        : "=r"(r[0]), "=r"(r[1]), "=r"(r[2]), "=r"(r[3]) : "r"(a));
}
__device__ __forceinline__ void mma16(float c[4], const unsigned a[4],
                                      unsigned b0, unsigned b1) {
    asm volatile(
        "mma.sync.aligned.m16n8k16.row.col.f32.f16.f16.f32 "
        "{%0,%1,%2,%3},{%4,%5,%6,%7},{%8,%9},{%0,%1,%2,%3};"
        : "+f"(c[0]), "+f"(c[1]), "+f"(c[2]), "+f"(c[3])
        : "r"(a[0]), "r"(a[1]), "r"(a[2]), "r"(a[3]), "r"(b0), "r"(b1));
}
__device__ __forceinline__ void split2x(float a, float b, uint32_t& hi, uint32_t& lo) {
    __half2 h = __floats2half2_rn(a, b);
    float2 hf = __half22float2(h);
    __half2 l = __floats2half2_rn(a - hf.x, b - hf.y);
    hi = *(uint32_t*)&h;
    lo = *(uint32_t*)&l;
}
__device__ __forceinline__ uint32_t pack_h2(float a, float b) {
    __half2 h = __floats2half2_rn(a, b);
    return *(uint32_t*)&h;
}
#define CP16(dst, src) \
    asm volatile("cp.async.cg.shared.global [%0], [%1], 16;" \
                 :: "r"(dst), "l"(src) : "memory")
#define CPCOMMIT() asm volatile("cp.async.commit_group;" ::: "memory")
#define CPWAIT0()  asm volatile("cp.async.wait_group 0;" ::: "memory")

// ---------------------------------------------------------------------------
// Fused projections (R15-proven). z = 0:Q scaled by log2(e)/8, 1:K, 2:V.
// BM=128 BN=64 BK=32. A plain fp16, W 2-term: acc = Ah*Wh + Ah*Wl.
// ---------------------------------------------------------------------------
__global__ __launch_bounds__(256, 2) void proj_hmma(
    const float* __restrict__ Qin, const float* __restrict__ Kin,
    const float* __restrict__ Vin,
    const float* __restrict__ Wq, const float* __restrict__ bq,
    const float* __restrict__ Wk,
    const float* __restrict__ Wv, const float* __restrict__ bv)
{
    const float *A, *W, *bias;
    __half *C;
    float scale;
    if (blockIdx.z == 0)      { A = Qin; W = Wq; bias = bq;      C = g_q;
                                scale = 0.18033688f; }   // (1/8)*log2(e)
    else if (blockIdx.z == 1) { A = Kin; W = Wk; bias = nullptr; C = g_k; scale = 1.f; }
    else                      { A = Vin; W = Wv; bias = bv;      C = g_v; scale = 1.f; }

    __shared__ __half Ah[128][40];
    __shared__ __half Wh[64][40], Wl[64][40];

    const int tid = threadIdx.x, warp = tid >> 5, lane = tid & 31;
    const int g = lane >> 2, tg = lane & 3;
    const int wm = warp & 3, wn = warp >> 2;
    const int bm = blockIdx.y * 128, bn = blockIdx.x * 64;

    const uint32_t ah_b = smem_u32(Ah);
    const uint32_t wh_b = smem_u32(Wh), wl_b = smem_u32(Wl);
    const int lrow = lane & 15, lcol8 = (lane >> 4) << 3;

    float acc[2][4][4];
#pragma unroll
    for (int i = 0; i < 2; ++i)
#pragma unroll
        for (int j = 0; j < 4; ++j)
#pragma unroll
            for (int t = 0; t < 4; ++t) acc[i][j][t] = 0.f;

    for (int k0 = 0; k0 < DM; k0 += 32) {
        __syncthreads();
#pragma unroll
        for (int i = 0; i < 4; ++i) {            // A: 128x32, plain fp16
            int f4 = tid + i * 256;
            int r = f4 >> 3, c4 = (f4 & 7) * 4;
            float4 v = *(const float4*)(A + (size_t)(bm + r) * DM + k0 + c4);
            *(uint32_t*)&Ah[r][c4]     = pack_h2(v.x, v.y);
            *(uint32_t*)&Ah[r][c4 + 2] = pack_h2(v.z, v.w);
        }
#pragma unroll
        for (int i = 0; i < 2; ++i) {            // W: 64x32, hi/lo
            int f4 = tid + i * 256;
            int r = f4 >> 3, c4 = (f4 & 7) * 4;
            float4 v = *(const float4*)(W + (size_t)(bn + r) * DM + k0 + c4);
            uint32_t h0, l0, h1, l1;
            split2x(v.x, v.y, h0, l0);
            split2x(v.z, v.w, h1, l1);
            *(uint32_t*)&Wh[r][c4] = h0; *(uint32_t*)&Wh[r][c4 + 2] = h1;
            *(uint32_t*)&Wl[r][c4] = l0; *(uint32_t*)&Wl[r][c4 + 2] = l1;
        }
        __syncthreads();

#pragma unroll
        for (int kk = 0; kk < 32; kk += 16) {
            unsigned a_h[2][4], b_h[2][4], b_l[2][4];
#pragma unroll
            for (int mf = 0; mf < 2; ++mf) {
                uint32_t off = (uint32_t)((wm * 32 + mf * 16 + lrow) * 40 + kk + lcol8) * 2;
                ldm4(a_h[mf], ah_b + off);
            }
#pragma unroll
            for (int nh = 0; nh < 2; ++nh) {
                uint32_t off = (uint32_t)((wn * 32 + nh * 16 + lrow) * 40 + kk + lcol8) * 2;
                ldm4(b_h[nh], wh_b + off);
                ldm4(b_l[nh], wl_b + off);
            }
#pragma unroll
            for (int mf = 0; mf < 2; ++mf)
#pragma unroll
                for (int nh = 0; nh < 2; ++nh)
#pragma unroll
                    for (int j = 0; j < 2; ++j) {
                        int nf = nh * 2 + j;
                        mma16(acc[mf][nf], a_h[mf], b_h[nh][j], b_h[nh][2 + j]);
                        mma16(acc[mf][nf], a_h[mf], b_l[nh][j], b_l[nh][2 + j]);
                    }
        }
    }

#pragma unroll
    for (int mf = 0; mf < 2; ++mf)
#pragma unroll
        for (int nf = 0; nf < 4; ++nf) {
            int r = bm + wm * 32 + mf * 16 + g;
            int c = bn + wn * 32 + (nf >> 1) * 16 + (nf & 1) * 8 + 2 * tg;
            float b0 = 0.f, b1 = 0.f;
            if (bias) { float2 bb = *(const float2*)(bias + c); b0 = bb.x; b1 = bb.y; }
            *(uint32_t*)(C + (size_t)r * (NH * DK) + c) =
                pack_h2((acc[mf][nf][0] + b0) * scale, (acc[mf][nf][1] + b1) * scale);
            *(uint32_t*)(C + (size_t)(r + 8) * (NH * DK) + c) =
                pack_h2((acc[mf][nf][2] + b0) * scale, (acc[mf][nf][3] + b1) * scale);
        }
}

// ---------------------------------------------------------------------------
// Flash attention, KV tile 64 (fixed per-tile costs amortized 2x), plain fp16,
// double-buffered cp.async (R8-proven schedule), exp2 softmax.
// smem (halves): Q 0..9216, K0 @9216 (+buf*4608), V0 @18432 (+buf*4608);
// MBW (4 words) @ byte 55296. Total 55328 B.
// ---------------------------------------------------------------------------
#define ATTN_SMEM 55328
#define KVB 9216   // bytes per KV buffer (4608 halves = 64 rows x 72)

__global__ __launch_bounds__(256, 2) void attn_kv64(
    const int* __restrict__ mask, float* __restrict__ out)
{
    extern __shared__ __half sm[];
    const uint32_t smb = smem_u32(sm);
    const uint32_t qh_base = smb;
    const uint32_t kh0 = smb + 9216 * 2;
    const uint32_t vh0 = smb + 18432 * 2;
    uint32_t* MBW = (uint32_t*)((char*)sm + 55296);

    const int tid = threadIdx.x, warp = tid >> 5, lane = tid & 31;
    const int g = lane >> 2, tg = lane & 3;
    const int b = blockIdx.z, h = blockIdx.y;
    const int q0 = blockIdx.x * 128;

    const int lrow = lane & 15, lcol8 = (lane >> 4) << 3;
    const int kvr  = (lane & 7) + ((lane >> 4) << 3);   // trans-ldmatrix row
    const int dcol = ((lane >> 3) & 1) * 8;
    // KV copy geometry: row = tid>>2 (0..63), 16-half span at (tid&3)*16
    const int cr = tid >> 2, cc = (tid & 3) * 16;
    const uint32_t cpo = (uint32_t)(cr * 72 + cc) * 2;

    float o[8][4];
#pragma unroll
    for (int i = 0; i < 8; ++i)
#pragma unroll
        for (int j = 0; j < 4; ++j) o[i][j] = 0.f;
    float mrA = -INFINITY, mrB = -INFINITY, lrA = 0.f, lrB = 0.f;
    float sa[8][4];

    // ---- prologue: stage Q + KV tile 0 + masks ----
    {
        int qrow = tid >> 1, qcb = (tid & 1) * 32;
        size_t qg = (size_t)(b * LQ + q0 + qrow) * (NH * DK) + h * DK + qcb;
        uint32_t qdh = qh_base + (uint32_t)(qrow * 72 + qcb) * 2;
#pragma unroll
        for (int j = 0; j < 4; ++j)
            CP16(qdh + j * 16, g_q + qg + j * 8);
        size_t g0 = (size_t)(b * LK + cr) * (NH * DK) + h * DK + cc;
        CP16(kh0 + cpo, g_k + g0);      CP16(kh0 + cpo + 16, g_k + g0 + 8);
        CP16(vh0 + cpo, g_v + g0);      CP16(vh0 + cpo + 16, g_v + g0 + 8);
        CPCOMMIT();
        if (warp == 0) {
            uint32_t b0 = __ballot_sync(0xffffffffu, mask[b * LK + lane] != 0);
            uint32_t b1 = __ballot_sync(0xffffffffu, mask[b * LK + 32 + lane] != 0);
            if (lane == 0) { MBW[0] = b0; MBW[1] = b1; }
        }
        CPWAIT0();
        __syncthreads();
    }

// One tile: wait copies of tile T (in BUF), prefetch T+1 into BUF^1,
// compute S, softmax, PV.
#define TILE_STEP(BUF, KT) do {                                               \
    if ((KT) + 64 < LK) {                                                     \
        int ktt = (KT) + 64;                                                  \
        size_t goff = (size_t)(b * LK + ktt + cr) * (NH * DK) + h * DK + cc;  \
        CP16(kh0 + ((BUF) ^ 1) * KVB + cpo, g_k + goff);                      \
        CP16(kh0 + ((BUF) ^ 1) * KVB + cpo + 16, g_k + goff + 8);             \
        CP16(vh0 + ((BUF) ^ 1) * KVB + cpo, g_v + goff);                      \
        CP16(vh0 + ((BUF) ^ 1) * KVB + cpo + 16, g_v + goff + 8);             \
        if (warp == 0) {                                                      \
            uint32_t b0 = __ballot_sync(0xffffffffu,                          \
                               mask[b * LK + ktt + lane] != 0);               \
            uint32_t b1 = __ballot_sync(0xffffffffu,                          \
                               mask[b * LK + ktt + 32 + lane] != 0);          \
            if (lane == 0) {                                                  \
                MBW[((BUF) ^ 1) * 2] = b0; MBW[((BUF) ^ 1) * 2 + 1] = b1;     \
            }                                                                 \
        }                                                                     \
    }                                                                         \
    CPCOMMIT();                                                               \
    /* ---- S = Q*K (16 x 64 per warp) ---- */                                \
    _Pragma("unroll")                                                         \
    for (int nf = 0; nf < 8; ++nf)                                            \
        { sa[nf][0]=0.f; sa[nf][1]=0.f; sa[nf][2]=0.f; sa[nf][3]=0.f; }       \
    _Pragma("unroll")                                                         \
    for (int kk = 0; kk < 4; ++kk) {                                          \
        unsigned qa[4];                                                       \
        uint32_t qoff = (uint32_t)((warp * 16 + lrow) * 72 + kk * 16 + lcol8) * 2; \
        ldm4(qa, qh_base + qoff);                                             \
        _Pragma("unroll")                                                     \
        for (int nh = 0; nh < 4; ++nh) {                                      \
            unsigned kb[4];                                                   \
            uint32_t koff = (uint32_t)((nh * 16 + lrow) * 72 + kk * 16 + lcol8) * 2; \
            ldm4(kb, kh0 + (BUF) * KVB + koff);                               \
            mma16(sa[nh * 2 + 0], qa, kb[0], kb[2]);                          \
            mma16(sa[nh * 2 + 1], qa, kb[1], kb[3]);                          \
        }                                                                     \
    }                                                                         \
    /* ---- mask + row max ---- */                                            \
    const uint32_t mb0 = MBW[(BUF) * 2], mb1 = MBW[(BUF) * 2 + 1];            \
    float mA = NEGV, mBv = NEGV;                                              \
    _Pragma("unroll")                                                         \
    for (int nf = 0; nf < 8; ++nf) {                                          \
        uint32_t mw = (nf < 4) ? mb0 : mb1;                                   \
        int c0 = (nf & 3) * 8 + 2 * tg;                                       \
        bool k0 = (mw >> c0) & 1u;                                            \
        bool k1 = (mw >> (c0 + 1)) & 1u;                                      \
        sa[nf][0] = k0 ? sa[nf][0] : NEGV;                                    \
        sa[nf][1] = k1 ? sa[nf][1] : NEGV;                                    \
        sa[nf][2] = k0 ? sa[nf][2] : NEGV;                                    \
        sa[nf][3] = k1 ? sa[nf][3] : NEGV;                                    \
        mA = fmaxf(mA, fmaxf(sa[nf][0], sa[nf][1]));                          \
        mBv = fmaxf(mBv, fmaxf(sa[nf][2], sa[nf][3]));                        \
    }                                                                         \
    mA = fmaxf(mA, __shfl_xor_sync(0xffffffffu, mA, 1));                      \
    mA = fmaxf(mA, __shfl_xor_sync(0xffffffffu, mA, 2));                      \
    mBv = fmaxf(mBv, __shfl_xor_sync(0xffffffffu, mBv, 1));                   \
    mBv = fmaxf(mBv, __shfl_xor_sync(0xffffffffu, mBv, 2));                   \
    float mnA = fmaxf(mrA, mA), mnB = fmaxf(mrB, mBv);                        \
    float alA = exp2f(mrA - mnA), alB = exp2f(mrB - mnB);                     \
    mrA = mnA; mrB = mnB;                                                     \
    /* ---- exp + pack P frags ---- */                                        \
    unsigned pah[4][4];                                                       \
    float lsA = 0.f, lsB = 0.f;                                               \
    _Pragma("unroll")                                                         \
    for (int jk = 0; jk < 4; ++jk) {                                          \
        _Pragma("unroll")                                                     \
        for (int t2 = 0; t2 < 2; ++t2) {                                      \
            int nf = jk * 2 + t2;                                             \
            float p0 = exp2f(sa[nf][0] - mnA);                                \
            float p1 = exp2f(sa[nf][1] - mnA);                                \
            float p2 = exp2f(sa[nf][2] - mnB);                                \
            float p3 = exp2f(sa[nf][3] - mnB);                                \
            lsA += p0 + p1; lsB += p2 + p3;                                   \
            pah[jk][2 * t2]     = pack_h2(p0, p1);                            \
            pah[jk][2 * t2 + 1] = pack_h2(p2, p3);                            \
        }                                                                     \
    }                                                                         \
    lsA += __shfl_xor_sync(0xffffffffu, lsA, 1);                              \
    lsA += __shfl_xor_sync(0xffffffffu, lsA, 2);                              \
    lsB += __shfl_xor_sync(0xffffffffu, lsB, 1);                              \
    lsB += __shfl_xor_sync(0xffffffffu, lsB, 2);                              \
    lrA = lrA * alA + lsA;                                                    \
    lrB = lrB * alB + lsB;                                                    \
    /* ---- rescale O, then O += P V ---- */                                  \
    _Pragma("unroll")                                                         \
    for (int nf = 0; nf < 8; ++nf) {                                          \
        o[nf][0] *= alA; o[nf][1] *= alA;                                     \
        o[nf][2] *= alB; o[nf][3] *= alB;                                     \
    }                                                                         \
    _Pragma("unroll")                                                         \
    for (int jk = 0; jk < 4; ++jk) {                                          \
        _Pragma("unroll")                                                     \
        for (int dh = 0; dh < 4; ++dh) {                                      \
            unsigned vb[4];                                                   \
            uint32_t voff = (uint32_t)((jk * 16 + kvr) * 72 + dh * 16 + dcol) * 2; \
            ldm4t(vb, vh0 + (BUF) * KVB + voff);                              \
            mma16(o[dh * 2 + 0], pah[jk], vb[0], vb[2]);                      \
            mma16(o[dh * 2 + 1], pah[jk], vb[1], vb[3]);                      \
        }                                                                     \
    }                                                                         \
    CPWAIT0();   /* copies for next tile complete */                          \
    __syncthreads();                                                          \
} while (0)

#pragma unroll 1
    for (int kt = 0; kt < LK; kt += 128) {
        TILE_STEP(0, kt);
        TILE_STEP(1, kt + 64);
    }
#undef TILE_STEP

    // ---- normalize + store ----
    {
        float iA = 1.f / lrA, iB = 1.f / lrB;
        float* o0 = out + (size_t)(b * LQ + q0 + warp * 16 + g) * (NH * DK) + h * DK;
        float* o1 = o0 + (size_t)8 * (NH * DK);
#pragma unroll
        for (int nf = 0; nf < 8; ++nf) {
            int c = (nf >> 1) * 16 + (nf & 1) * 8 + 2 * tg;
            *(float2*)(o0 + c) = make_float2(o[nf][0] * iA, o[nf][1] * iA);
            *(float2*)(o1 + c) = make_float2(o[nf][2] * iB, o[nf][3] * iB);
        }
    }
}

// ---------------------------------------------------------------------------
extern "C" void kernel_launch(void* const* d_in, const int* in_sizes, int n_in,
                              void* d_out, int out_size)
{
    const float* Q    = (const float*)d_in[0];
    const float* K    = (const float*)d_in[1];
    const float* V    = (const float*)d_in[2];
    const int*   mask = (const int*)d_in[3];
    const float* Wq   = (const float*)d_in[4];
    const float* bq   = (const float*)d_in[5];
    const float* Wk   = (const float*)d_in[6];
    const float* Wv   = (const float*)d_in[7];
    const float* bv   = (const float*)d_in[8];
    float* out = (float*)d_out;

    cudaFuncSetAttribute(attn_kv64, cudaFuncAttributeMaxDynamicSharedMemorySize,
                         ATTN_SMEM);

    dim3 gproj((NH * DK) / 64, (BB * LQ) / 128, 3);  // (16, 64, 3)
    proj_hmma<<<gproj, 256>>>(Q, K, V, Wq, bq, Wk, Wv, bv);

    dim3 gattn(LQ / 128, NH, BB);  // (16, 16, 4)
    attn_kv64<<<gattn, 256, ATTN_SMEM>>>(mask, out);
}

// round 17
// speedup vs baseline: 1.6814x; 1.0472x over previous
#include <cuda_runtime.h>
#include <cuda_fp16.h>
#include <math.h>
#include <stdint.h>

#define BB 4
#define LQ 2048
#define LK 2048
#define DM 1024
#define NH 16
#define DK 64
#define NEGV -1000000000.0f

// Projected q/k/v, plain fp16 (Q pre-scaled by log2(e)/8): [B*LEN, NH*DK]
__device__ __half g_q[BB * LQ * NH * DK];
__device__ __half g_k[BB * LK * NH * DK];
__device__ __half g_v[BB * LK * NH * DK];

// Pre-split projection operands: A plain fp16, W hi/lo fp16.
__device__ __half i_q[BB * LQ * DM], i_k[BB * LK * DM], i_v[BB * LK * DM];
__device__ __half w_qh[NH * DK * DM], w_ql[NH * DK * DM];
__device__ __half w_kh[NH * DK * DM], w_kl[NH * DK * DM];
__device__ __half w_vh[NH * DK * DM], w_vl[NH * DK * DM];

__device__ __forceinline__ uint32_t smem_u32(const void* p) {
    uint32_t a;
    asm("{ .reg .u64 t; cvta.to.shared.u64 t, %1; cvt.u32.u64 %0, t; }"
        : "=r"(a) : "l"(p));
    return a;
}
__device__ __forceinline__ void ldm4(unsigned r[4], uint32_t a) {
    asm volatile("ldmatrix.sync.aligned.m8n8.x4.shared.b16 {%0,%1,%2,%3}, [%4];"
        : "=r"(r[0]), "=r"(r[1]), "=r"(r[2]), "=r"(r[3]) : "r"(a));
}
__device__ __forceinline__ void ldm4t(unsigned r[4], uint32_t a) {
    asm volatile("ldmatrix.sync.aligned.m8n8.x4.trans.shared.b16 {%0,%1,%2,%3}, [%4];"
        : "=r"(r[0]), "=r"(r[1]), "=r"(r[2]), "=r"(r[3]) : "r"(a));
}
__device__ __forceinline__ void mma16(float c[4], const unsigned a[4],
                                      unsigned b0, unsigned b1) {
    asm volatile(
        "mma.sync.aligned.m16n8k16.row.col.f32.f16.f16.f32 "
        "{%0,%1,%2,%3},{%4,%5,%6,%7},{%8,%9},{%0,%1,%2,%3};"
        : "+f"(c[0]), "+f"(c[1]), "+f"(c[2]), "+f"(c[3])
        : "r"(a[0]), "r"(a[1]), "r"(a[2]), "r"(a[3]), "r"(b0), "r"(b1));
}
__device__ __forceinline__ void split2x(float a, float b, uint32_t& hi, uint32_t& lo) {
    __half2 h = __floats2half2_rn(a, b);
    float2 hf = __half22float2(h);
    __half2 l = __floats2half2_rn(a - hf.x, b - hf.y);
    hi = *(uint32_t*)&h;
    lo = *(uint32_t*)&l;
}
__device__ __forceinline__ uint32_t pack_h2(float a, float b) {
    __half2 h = __floats2half2_rn(a, b);
    return *(uint32_t*)&h;
}
#define CP16(dst, src) \
    asm volatile("cp.async.cg.shared.global [%0], [%1], 16;" \
                 :: "r"(dst), "l"(src) : "memory")
#define CPCOMMIT() asm volatile("cp.async.commit_group;" ::: "memory")
#define CPWAIT0()  asm volatile("cp.async.wait_group 0;" ::: "memory")

// ---------------------------------------------------------------------------
// Pre-split: A inputs -> plain fp16; W weights -> fp16 hi/lo. DRAM-bound.
// ---------------------------------------------------------------------------
__global__ __launch_bounds__(256) void presplit(
    const float* __restrict__ Qin, const float* __restrict__ Kin,
    const float* __restrict__ Vin,
    const float* __restrict__ Wq, const float* __restrict__ Wk,
    const float* __restrict__ Wv)
{
    const float *A, *W;
    __half *ao, *wh, *wl;
    if (blockIdx.z == 0)      { A = Qin; W = Wq; ao = i_q; wh = w_qh; wl = w_ql; }
    else if (blockIdx.z == 1) { A = Kin; W = Wk; ao = i_k; wh = w_kh; wl = w_kl; }
    else                      { A = Vin; W = Wv; ao = i_v; wh = w_vh; wl = w_vl; }

    const int stride = gridDim.x * blockDim.x;
    const int t0 = blockIdx.x * blockDim.x + threadIdx.x;

    const int NA = BB * LQ * DM / 4;
    for (int idx = t0; idx < NA; idx += stride) {
        float4 v = ((const float4*)A)[idx];
        ((uint2*)ao)[idx] = make_uint2(pack_h2(v.x, v.y), pack_h2(v.z, v.w));
    }
    const int NW = NH * DK * DM / 4;
    for (int idx = t0; idx < NW; idx += stride) {
        float4 v = ((const float4*)W)[idx];
        uint32_t h0, l0, h1, l1;
        split2x(v.x, v.y, h0, l0);
        split2x(v.z, v.w, h1, l1);
        ((uint2*)wh)[idx] = make_uint2(h0, h1);
        ((uint2*)wl)[idx] = make_uint2(l0, l1);
    }
}

// ---------------------------------------------------------------------------
// Projection GEMM: BK=64, double-buffered CP16 staging (attention-style
// schedule). z = 0:Q (scale log2(e)/8), 1:K, 2:V. A fp16, W 2-term.
// smem/buffer: A 128x72 (18432 B) + Wh 64x72 (9216) + Wl (9216) = 36864 B;
// 2 buffers = 73728 B.
// ---------------------------------------------------------------------------
#define PJ_WH 18432
#define PJ_WL 27648
#define PJ_BUF 36864
#define PJ_SMEM 73728

__global__ __launch_bounds__(256, 2) void proj_kv64(
    const float* __restrict__ bq, const float* __restrict__ bv)
{
    const __half *Ag, *Wgh, *Wgl;
    const float* bias;
    __half *C;
    float scale;
    if (blockIdx.z == 0)      { Ag = i_q; Wgh = w_qh; Wgl = w_ql; bias = bq;
                                C = g_q; scale = 0.18033688f; }  // (1/8)*log2(e)
    else if (blockIdx.z == 1) { Ag = i_k; Wgh = w_kh; Wgl = w_kl; bias = nullptr;
                                C = g_k; scale = 1.f; }
    else                      { Ag = i_v; Wgh = w_vh; Wgl = w_vl; bias = bv;
                                C = g_v; scale = 1.f; }

    extern __shared__ __half psm[];
    const uint32_t smb = smem_u32(psm);

    const int tid = threadIdx.x, warp = tid >> 5, lane = tid & 31;
    const int g = lane >> 2, tg = lane & 3;
    const int wm = warp & 3, wn = warp >> 2;
    const int bm = blockIdx.y * 128, bn = blockIdx.x * 64;
    const int lrow = lane & 15, lcol8 = (lane >> 4) << 3;

    // copy geometry: A row = tid>>1 (0..127), 32-half span at (tid&1)*32
    //                W row = tid>>2 (0..63), 16-half span at (tid&3)*16
    const int ar = tid >> 1, ac = (tid & 1) * 32;
    const int wr = tid >> 2, wc = (tid & 3) * 16;
    const uint32_t apo = (uint32_t)(ar * 72 + ac) * 2;
    const uint32_t wpo = (uint32_t)(wr * 72 + wc) * 2;

    float acc[2][4][4];
#pragma unroll
    for (int i = 0; i < 2; ++i)
#pragma unroll
        for (int j = 0; j < 4; ++j)
#pragma unroll
            for (int t = 0; t < 4; ++t) acc[i][j][t] = 0.f;

#define PJ_COPY(BUF, K0) do {                                                 \
    uint32_t ab = smb + (BUF) * PJ_BUF + apo;                                 \
    const __half* asrc = Ag + (size_t)(bm + ar) * DM + (K0) + ac;             \
    CP16(ab, asrc);           CP16(ab + 16, asrc + 8);                        \
    CP16(ab + 32, asrc + 16); CP16(ab + 48, asrc + 24);                       \
    uint32_t whb = smb + (BUF) * PJ_BUF + PJ_WH + wpo;                        \
    const __half* whs = Wgh + (size_t)(bn + wr) * DM + (K0) + wc;             \
    CP16(whb, whs); CP16(whb + 16, whs + 8);                                  \
    uint32_t wlb = smb + (BUF) * PJ_BUF + PJ_WL + wpo;                        \
    const __half* wls = Wgl + (size_t)(bn + wr) * DM + (K0) + wc;             \
    CP16(wlb, wls); CP16(wlb + 16, wls + 8);                                  \
} while (0)

// One BK=64 step: prefetch next into BUF^1, compute on BUF, wait, sync.
#define PJ_STEP(BUF, K0) do {                                                 \
    if ((K0) + 64 < DM) PJ_COPY((BUF) ^ 1, (K0) + 64);                        \
    CPCOMMIT();                                                               \
    const uint32_t ab = smb + (BUF) * PJ_BUF;                                 \
    const uint32_t whb = ab + PJ_WH;                                          \
    const uint32_t wlb = ab + PJ_WL;                                          \
    _Pragma("unroll")                                                         \
    for (int kk = 0; kk < 4; ++kk) {                                          \
        unsigned a_h[2][4], b_h[2][4], b_l[2][4];                             \
        _Pragma("unroll")                                                     \
        for (int mf = 0; mf < 2; ++mf) {                                      \
            uint32_t off = (uint32_t)((wm * 32 + mf * 16 + lrow) * 72 + kk * 16 + lcol8) * 2; \
            ldm4(a_h[mf], ab + off);                                          \
        }                                                                     \
        _Pragma("unroll")                                                     \
        for (int nh = 0; nh < 2; ++nh) {                                      \
            uint32_t off = (uint32_t)((wn * 32 + nh * 16 + lrow) * 72 + kk * 16 + lcol8) * 2; \
            ldm4(b_h[nh], whb + off);                                         \
            ldm4(b_l[nh], wlb + off);                                         \
        }                                                                     \
        _Pragma("unroll")                                                     \
        for (int mf = 0; mf < 2; ++mf)                                        \
            _Pragma("unroll")                                                 \
            for (int nh = 0; nh < 2; ++nh)                                    \
                _Pragma("unroll")                                             \
                for (int j = 0; j < 2; ++j) {                                 \
                    int nf = nh * 2 + j;                                      \
                    mma16(acc[mf][nf], a_h[mf], b_h[nh][j], b_h[nh][2 + j]);  \
                    mma16(acc[mf][nf], a_h[mf], b_l[nh][j], b_l[nh][2 + j]);  \
                }                                                             \
    }                                                                         \
    CPWAIT0();                                                                \
    __syncthreads();                                                          \
} while (0)

    // prologue: buffer 0 <- k0=0
    PJ_COPY(0, 0);
    CPCOMMIT();
    CPWAIT0();
    __syncthreads();

#pragma unroll 1
    for (int k0 = 0; k0 < DM; k0 += 128) {
        PJ_STEP(0, k0);
        PJ_STEP(1, k0 + 64);
    }
#undef PJ_STEP
#undef PJ_COPY

    // Epilogue: bias + scale, store plain fp16.
#pragma unroll
    for (int mf = 0; mf < 2; ++mf)
#pragma unroll
        for (int nf = 0; nf < 4; ++nf) {
            int r = bm + wm * 32 + mf * 16 + g;
            int c = bn + wn * 32 + (nf >> 1) * 16 + (nf & 1) * 8 + 2 * tg;
            float b0 = 0.f, b1 = 0.f;
            if (bias) { float2 bb = *(const float2*)(bias + c); b0 = bb.x; b1 = bb.y; }
            *(uint32_t*)(C + (size_t)r * (NH * DK) + c) =
                pack_h2((acc[mf][nf][0] + b0) * scale, (acc[mf][nf][1] + b1) * scale);
            *(uint32_t*)(C + (size_t)(r + 8) * (NH * DK) + c) =
                pack_h2((acc[mf][nf][2] + b0) * scale, (acc[mf][nf][3] + b1) * scale);
        }
}

// ---------------------------------------------------------------------------
// Flash attention (R16 version, unchanged — proven 268us). KV tile 64,
// plain fp16, double-buffered cp.async, exp2 softmax.
// ---------------------------------------------------------------------------
#define ATTN_SMEM 55328
#define KVB 9216   // bytes per KV buffer (4608 halves = 64 rows x 72)

__global__ __launch_bounds__(256, 2) void attn_kv64(
    const int* __restrict__ mask, float* __restrict__ out)
{
    extern __shared__ __half sm[];
    const uint32_t smb = smem_u32(sm);
    const uint32_t qh_base = smb;
    const uint32_t kh0 = smb + 9216 * 2;
    const uint32_t vh0 = smb + 18432 * 2;
    uint32_t* MBW = (uint32_t*)((char*)sm + 55296);

    const int tid = threadIdx.x, warp = tid >> 5, lane = tid & 31;
    const int g = lane >> 2, tg = lane & 3;
    const int b = blockIdx.z, h = blockIdx.y;
    const int q0 = blockIdx.x * 128;

    const int lrow = lane & 15, lcol8 = (lane >> 4) << 3;
    const int kvr  = (lane & 7) + ((lane >> 4) << 3);
    const int dcol = ((lane >> 3) & 1) * 8;
    const int cr = tid >> 2, cc = (tid & 3) * 16;
    const uint32_t cpo = (uint32_t)(cr * 72 + cc) * 2;

    float o[8][4];
#pragma unroll
    for (int i = 0; i < 8; ++i)
#pragma unroll
        for (int j = 0; j < 4; ++j) o[i][j] = 0.f;
    float mrA = -INFINITY, mrB = -INFINITY, lrA = 0.f, lrB = 0.f;
    float sa[8][4];

    // ---- prologue: stage Q + KV tile 0 + masks ----
    {
        int qrow = tid >> 1, qcb = (tid & 1) * 32;
        size_t qg = (size_t)(b * LQ + q0 + qrow) * (NH * DK) + h * DK + qcb;
        uint32_t qdh = qh_base + (uint32_t)(qrow * 72 + qcb) * 2;
#pragma unroll
        for (int j = 0; j < 4; ++j)
            CP16(qdh + j * 16, g_q + qg + j * 8);
        size_t g0 = (size_t)(b * LK + cr) * (NH * DK) + h * DK + cc;
        CP16(kh0 + cpo, g_k + g0);      CP16(kh0 + cpo + 16, g_k + g0 + 8);
        CP16(vh0 + cpo, g_v + g0);      CP16(vh0 + cpo + 16, g_v + g0 + 8);
        CPCOMMIT();
        if (warp == 0) {
            uint32_t b0 = __ballot_sync(0xffffffffu, mask[b * LK + lane] != 0);
            uint32_t b1 = __ballot_sync(0xffffffffu, mask[b * LK + 32 + lane] != 0);
            if (lane == 0) { MBW[0] = b0; MBW[1] = b1; }
        }
        CPWAIT0();
        __syncthreads();
    }

#define TILE_STEP(BUF, KT) do {                                               \
    if ((KT) + 64 < LK) {                                                     \
        int ktt = (KT) + 64;                                                  \
        size_t goff = (size_t)(b * LK + ktt + cr) * (NH * DK) + h * DK + cc;  \
        CP16(kh0 + ((BUF) ^ 1) * KVB + cpo, g_k + goff);                      \
        CP16(kh0 + ((BUF) ^ 1) * KVB + cpo + 16, g_k + goff + 8);             \
        CP16(vh0 + ((BUF) ^ 1) * KVB + cpo, g_v + goff);                      \
        CP16(vh0 + ((BUF) ^ 1) * KVB + cpo + 16, g_v + goff + 8);             \
        if (warp == 0) {                                                      \
            uint32_t b0 = __ballot_sync(0xffffffffu,                          \
                               mask[b * LK + ktt + lane] != 0);               \
            uint32_t b1 = __ballot_sync(0xffffffffu,                          \
                               mask[b * LK + ktt + 32 + lane] != 0);          \
            if (lane == 0) {                                                  \
                MBW[((BUF) ^ 1) * 2] = b0; MBW[((BUF) ^ 1) * 2 + 1] = b1;     \
            }                                                                 \
        }                                                                     \
    }                                                                         \
    CPCOMMIT();                                                               \
    _Pragma("unroll")                                                         \
    for (int nf = 0; nf < 8; ++nf)                                            \
        { sa[nf][0]=0.f; sa[nf][1]=0.f; sa[nf][2]=0.f; sa[nf][3]=0.f; }       \
    _Pragma("unroll")                                                         \
    for (int kk = 0; kk < 4; ++kk) {                                          \
        unsigned qa[4];                                                       \
        uint32_t qoff = (uint32_t)((warp * 16 + lrow) * 72 + kk * 16 + lcol8) * 2; \
        ldm4(qa, qh_base + qoff);                                             \
        _Pragma("unroll")                                                     \
        for (int nh = 0; nh < 4; ++nh) {                                      \
            unsigned kb[4];                                                   \
            uint32_t koff = (uint32_t)((nh * 16 + lrow) * 72 + kk * 16 + lcol8) * 2; \
            ldm4(kb, kh0 + (BUF) * KVB + koff);                               \
            mma16(sa[nh * 2 + 0], qa, kb[0], kb[2]);                          \
            mma16(sa[nh * 2 + 1], qa, kb[1], kb[3]);                          \
        }                                                                     \
    }                                                                         \
    const uint32_t mb0 = MBW[(BUF) * 2], mb1 = MBW[(BUF) * 2 + 1];            \
    float mA = NEGV, mBv = NEGV;                                              \
    _Pragma("unroll")                                                         \
    for (int nf = 0; nf < 8; ++nf) {                                          \
        uint32_t mw = (nf < 4) ? mb0 : mb1;                                   \
        int c0 = (nf & 3) * 8 + 2 * tg;                                       \
        bool k0 = (mw >> c0) & 1u;                                            \
        bool k1 = (mw >> (c0 + 1)) & 1u;                                      \
        sa[nf][0] = k0 ? sa[nf][0] : NEGV;                                    \
        sa[nf][1] = k1 ? sa[nf][1] : NEGV;                                    \
        sa[nf][2] = k0 ? sa[nf][2] : NEGV;                                    \
        sa[nf][3] = k1 ? sa[nf][3] : NEGV;                                    \
        mA = fmaxf(mA, fmaxf(sa[nf][0], sa[nf][1]));                          \
        mBv = fmaxf(mBv, fmaxf(sa[nf][2], sa[nf][3]));                        \
    }                                                                         \
    mA = fmaxf(mA, __shfl_xor_sync(0xffffffffu, mA, 1));                      \
    mA = fmaxf(mA, __shfl_xor_sync(0xffffffffu, mA, 2));                      \
    mBv = fmaxf(mBv, __shfl_xor_sync(0xffffffffu, mBv, 1));                   \
    mBv = fmaxf(mBv, __shfl_xor_sync(0xffffffffu, mBv, 2));                   \
    float mnA = fmaxf(mrA, mA), mnB = fmaxf(mrB, mBv);                        \
    float alA = exp2f(mrA - mnA), alB = exp2f(mrB - mnB);                     \
    mrA = mnA; mrB = mnB;                                                     \
    unsigned pah[4][4];                                                       \
    float lsA = 0.f, lsB = 0.f;                                               \
    _Pragma("unroll")                                                         \
    for (int jk = 0; jk < 4; ++jk) {                                          \
        _Pragma("unroll")                                                     \
        for (int t2 = 0; t2 < 2; ++t2) {                                      \
            int nf = jk * 2 + t2;                                             \
            float p0 = exp2f(sa[nf][0] - mnA);                                \
            float p1 = exp2f(sa[nf][1] - mnA);                                \
            float p2 = exp2f(sa[nf][2] - mnB);                                \
            float p3 = exp2f(sa[nf][3] - mnB);                                \
            lsA += p0 + p1; lsB += p2 + p3;                                   \
            pah[jk][2 * t2]     = pack_h2(p0, p1);                            \
            pah[jk][2 * t2 + 1] = pack_h2(p2, p3);                            \
        }                                                                     \
    }                                                                         \
    lsA += __shfl_xor_sync(0xffffffffu, lsA, 1);                              \
    lsA += __shfl_xor_sync(0xffffffffu, lsA, 2);                              \
    lsB += __shfl_xor_sync(0xffffffffu, lsB, 1);                              \
    lsB += __shfl_xor_sync(0xffffffffu, lsB, 2);                              \
    lrA = lrA * alA + lsA;                                                    \
    lrB = lrB * alB + lsB;                                                    \
    _Pragma("unroll")                                                         \
    for (int nf = 0; nf < 8; ++nf) {                                          \
        o[nf][0] *= alA; o[nf][1] *= alA;                                     \
        o[nf][2] *= alB; o[nf][3] *= alB;                                     \
    }                                                                         \
    _Pragma("unroll")                                                         \
    for (int jk = 0; jk < 4; ++jk) {                                          \
        _Pragma("unroll")                                                     \
        for (int dh = 0; dh < 4; ++dh) {                                      \
            unsigned vb[4];                                                   \
            uint32_t voff = (uint32_t)((jk * 16 + kvr) * 72 + dh * 16 + dcol) * 2; \
            ldm4t(vb, vh0 + (BUF) * KVB + voff);                              \
            mma16(o[dh * 2 + 0], pah[jk], vb[0], vb[2]);                      \
            mma16(o[dh * 2 + 1], pah[jk], vb[1], vb[3]);                      \
        }                                                                     \
    }                                                                         \
    CPWAIT0();                                                                \
    __syncthreads();                                                          \
} while (0)

#pragma unroll 1
    for (int kt = 0; kt < LK; kt += 128) {
        TILE_STEP(0, kt);
        TILE_STEP(1, kt + 64);
    }
#undef TILE_STEP

    // ---- normalize + store ----
    {
        float iA = 1.f / lrA, iB = 1.f / lrB;
        float* o0 = out + (size_t)(b * LQ + q0 + warp * 16 + g) * (NH * DK) + h * DK;
        float* o1 = o0 + (size_t)8 * (NH * DK);
#pragma unroll
        for (int nf = 0; nf < 8; ++nf) {
            int c = (nf >> 1) * 16 + (nf & 1) * 8 + 2 * tg;
            *(float2*)(o0 + c) = make_float2(o[nf][0] * iA, o[nf][1] * iA);
            *(float2*)(o1 + c) = make_float2(o[nf][2] * iB, o[nf][3] * iB);
        }
    }
}

// ---------------------------------------------------------------------------
extern "C" void kernel_launch(void* const* d_in, const int* in_sizes, int n_in,
                              void* d_out, int out_size)
{
    const float* Q    = (const float*)d_in[0];
    const float* K    = (const float*)d_in[1];
    const float* V    = (const float*)d_in[2];
    const int*   mask = (const int*)d_in[3];
    const float* Wq   = (const float*)d_in[4];
    const float* bq   = (const float*)d_in[5];
    const float* Wk   = (const float*)d_in[6];
    const float* Wv   = (const float*)d_in[7];
    const float* bv   = (const float*)d_in[8];
    float* out = (float*)d_out;

    cudaFuncSetAttribute(proj_kv64, cudaFuncAttributeMaxDynamicSharedMemorySize,
                         PJ_SMEM);
    cudaFuncSetAttribute(attn_kv64, cudaFuncAttributeMaxDynamicSharedMemorySize,
                         ATTN_SMEM);

    presplit<<<dim3(512, 1, 3), 256>>>(Q, K, V, Wq, Wk, Wv);

    dim3 gproj((NH * DK) / 64, (BB * LQ) / 128, 3);  // (16, 64, 3)
    proj_kv64<<<gproj, 256, PJ_SMEM>>>(bq, bv);

    dim3 gattn(LQ / 128, NH, BB);  // (16, 16, 4)
    attn_kv64<<<gattn, 256, ATTN_SMEM>>>(mask, out);
}